// round 1
// baseline (speedup 1.0000x reference)
#include <cuda_runtime.h>
#include <math.h>

#define BB 16
#define LL 1024
#define MM 21
#define PP 16
#define NN 64
#define DD 768
#define HH 8
#define EE 96
#define FF4 3072
#define NLAYER 3
#define FREQ 33
#define A2 32
#define PREDN 96
#define BMC (BB*MM)          /* 336 */
#define ROWS (BMC*NN)        /* 21504 */
#define EPSF 1e-5f

/* ---------------- scratch layout (floats) ---------------- */
#define OFF_MEAN   0u
#define OFF_STD    512u
#define OFF_PATCH  1024u          /* 344064 */
#define OFF_T      345088u        /* 3*4096  */
#define OFF_MU     357376u        /* 16384   */
#define OFF_RV     373760u        /* 16384   */
#define OFF_AD     390144u        /* 344064  */
#define OFF_BNSUM  734208u        /* 768     */
#define OFF_BNSQ   734976u        /* 768     */
#define OFF_OSMALL 735744u        /* 32256   */
#define OFF_H      768000u
#define OFF_Y      (OFF_H + 16515072u)
#define OFF_Q      (OFF_Y + 16515072u)
#define OFF_K      (OFF_Q + 16515072u)
#define OFF_V      (OFF_K + 16515072u)
#define OFF_O      (OFF_V + 16515072u)
#define OFF_SC     (OFF_O + 16515072u)
#define OFF_F4     (OFF_SC + 11010048u)
#define TOTAL_F    (OFF_F4 + 66060288u)   /* 176,928,768 floats = ~708 MB */

__device__ float g_buf[TOTAL_F];

/* ---------------- RevIN stats ---------------- */
__global__ void revin_stats_kernel(const float* __restrict__ x, float* __restrict__ mean,
                                   float* __restrict__ stdv) {
    int bm = blockIdx.x;              /* 0..335 */
    int b = bm / MM, m = bm % MM;
    const float* xp = x + (size_t)b * LL * MM + m;
    float s = 0.f, s2 = 0.f;
    for (int l = threadIdx.x; l < LL; l += 256) {
        float v = xp[(size_t)l * MM];
        s += v; s2 += v * v;
    }
    __shared__ float sh0[256], sh1[256];
    sh0[threadIdx.x] = s; sh1[threadIdx.x] = s2;
    __syncthreads();
    for (int off = 128; off > 0; off >>= 1) {
        if (threadIdx.x < off) { sh0[threadIdx.x] += sh0[threadIdx.x + off]; sh1[threadIdx.x] += sh1[threadIdx.x + off]; }
        __syncthreads();
    }
    if (threadIdx.x == 0) {
        float mu = sh0[0] * (1.f / LL);
        float var = sh1[0] * (1.f / LL) - mu * mu;
        mean[bm] = mu;
        stdv[bm] = sqrtf(var + EPSF);
    }
}

/* ---------------- patches (RevIN applied) ---------------- */
__global__ void patches_kernel(const float* __restrict__ x, const float* __restrict__ mean,
                               const float* __restrict__ stdv, const float* __restrict__ rw,
                               const float* __restrict__ rb, float* __restrict__ patches) {
    int idx = blockIdx.x * 256 + threadIdx.x;     /* < 344064 */
    int p = idx & 15;
    int n = (idx >> 4) & 63;
    int bm = idx >> 10;        /* b*21+m */
    int m = bm % MM;
    int b = bm / MM;
    int l = n * 16 + p;
    float v = x[(size_t)b * LL * MM + (size_t)l * MM + m];
    v = (v - mean[bm]) / stdv[bm] * rw[m] + rb[m];
    patches[idx] = v;
}

/* ---------------- composed spectral transform T (64x64 per layer) ---------------- */
__global__ void computeT_kernel(const float* __restrict__ wr, const float* __restrict__ wi,
                                float* __restrict__ T) {
    int lay = blockIdx.x;
    __shared__ float Ur[32][64], Ui[32][64];
    const float* wrp = wr + (size_t)lay * FREQ * A2;
    const float* wip = wi + (size_t)lay * FREQ * A2;
    const float c0 = 6.28318530717958647692f / 64.f;
    for (int e = threadIdx.x; e < 32 * 64; e += 256) {
        int d = e >> 6, n = e & 63;
        float sr = 0.f, si = 0.f;
        for (int kf = 0; kf < FREQ; ++kf) {
            float ang = c0 * (float)(kf * n);
            float cv, sv;
            sincosf(ang, &sv, &cv);
            sr += wrp[kf * A2 + d] * cv;
            si += wip[kf * A2 + d] * (-sv);
        }
        Ur[d][n] = sr; Ui[d][n] = si;
    }
    __syncthreads();
    for (int e = threadIdx.x; e < 64 * 64; e += 256) {
        int a = e >> 6, n = e & 63;
        float tval = Ur[0][n];               /* d=0 term, imag(DC) ignored by irfft */
        for (int d = 1; d < 32; ++d) {
            float ang = c0 * (float)(d * a);
            float cv, sv;
            sincosf(ang, &sv, &cv);
            tval += 2.f * (Ur[d][n] * cv - Ui[d][n] * sv);
        }
        T[lay * 4096 + e] = tval * (1.f / 64.f);
    }
}

/* ---------------- instance-norm stats over M ---------------- */
__global__ void pn_stats_kernel(const float* __restrict__ patches, float* __restrict__ mu,
                                float* __restrict__ rv) {
    int idx = blockIdx.x * 256 + threadIdx.x;    /* < 16384 : b*1024 + n*16 + p */
    int b = idx >> 10;
    int np = idx & 1023;
    const float* pp = patches + (size_t)b * 21504 + np;
    float s = 0.f, s2 = 0.f;
#pragma unroll
    for (int m = 0; m < MM; ++m) { float v = pp[m * 1024]; s += v; s2 += v * v; }
    float m0 = s * (1.f / MM);
    float var = s2 * (1.f / MM) - m0 * m0;
    mu[idx] = m0;
    rv[idx] = rsqrtf(var + EPSF);
}

/* ---------------- spectral mixing: ad = T @ pn (along patch axis) ---------------- */
__global__ void spect_kernel(const float* __restrict__ patches, const float* __restrict__ mu,
                             const float* __restrict__ rv, const float* __restrict__ g,
                             const float* __restrict__ be, const float* __restrict__ T,
                             float* __restrict__ ad) {
    int idx = blockIdx.x * 256 + threadIdx.x;    /* < 344064 */
    int p = idx & 15;
    int a = (idx >> 4) & 63;
    int bm = idx >> 10;
    int m = bm % MM;
    int b = bm / MM;
    float gm = g[m], bm_ = be[m];
    const float* pp  = patches + (size_t)bm * 1024 + p;
    const float* mup = mu + b * 1024 + p;
    const float* rvp = rv + b * 1024 + p;
    const float* Tp  = T + a * 64;
    float acc = 0.f;
#pragma unroll 8
    for (int n = 0; n < 64; ++n) {
        float pn = (pp[n * 16] - mup[n * 16]) * rvp[n * 16] * gm + bm_;
        acc += Tp[n] * pn;
    }
    ad[idx] = acc;
}

/* ---------------- embeddings (K=16 projection) ---------------- */
__global__ void embed0_kernel(const float* __restrict__ patches, const float* __restrict__ inw,
                              const float* __restrict__ inb, float* __restrict__ Hout) {
    int idx = blockIdx.x * 256 + threadIdx.x;    /* < ROWS*DD */
    int row = idx / DD, d = idx - row * DD;
    const float* pr = patches + (size_t)row * PP;
    const float* wrow = inw + (size_t)d * PP;
    float s = inb[d];
#pragma unroll
    for (int p = 0; p < PP; ++p) s += pr[p] * wrow[p];
    Hout[idx] = s;
}

__global__ void embed_add_kernel(const float* __restrict__ Hin, const float* __restrict__ ad,
                                 const float* __restrict__ inw, const float* __restrict__ inb,
                                 float* __restrict__ Y) {
    int idx = blockIdx.x * 256 + threadIdx.x;
    int row = idx / DD, d = idx - row * DD;
    const float* ar = ad + (size_t)row * PP;
    const float* wrow = inw + (size_t)d * PP;
    float s = inb[d] + Hin[idx];
#pragma unroll
    for (int p = 0; p < PP; ++p) s += ar[p] * wrow[p];
    Y[idx] = s;
}

/* ---------------- tiled fp32 GEMM: C = A(MxK) * W^T(NxK) + bias [+R] [relu] ---------------- */
template<int RELU, int RES>
__launch_bounds__(256, 2)
__global__ void sgemm_kernel(const float* __restrict__ A, const float* __restrict__ W,
                             const float* __restrict__ bias, const float* __restrict__ Rsrc,
                             float* __restrict__ C, int M, int N, int K) {
    __shared__ float As[8][128];
    __shared__ float Ws[8][128];
    const int t = threadIdx.x;
    const int m0 = blockIdx.y * 128;
    const int n0 = blockIdx.x * 128;
    const int lr = t >> 1;
    const int lk = (t & 1) << 2;
    const float* Ag = A + (size_t)(m0 + lr) * K + lk;
    const float* Wg = W + (size_t)(n0 + lr) * K + lk;
    const int tx = t & 15, ty = t >> 4;

    float acc[8][8];
#pragma unroll
    for (int i = 0; i < 8; ++i)
#pragma unroll
        for (int j = 0; j < 8; ++j) acc[i][j] = 0.f;

    for (int k0 = 0; k0 < K; k0 += 8) {
        float4 av = *(const float4*)(Ag + k0);
        float4 wv = *(const float4*)(Wg + k0);
        __syncthreads();
        As[lk + 0][lr] = av.x; As[lk + 1][lr] = av.y; As[lk + 2][lr] = av.z; As[lk + 3][lr] = av.w;
        Ws[lk + 0][lr] = wv.x; Ws[lk + 1][lr] = wv.y; Ws[lk + 2][lr] = wv.z; Ws[lk + 3][lr] = wv.w;
        __syncthreads();
#pragma unroll
        for (int kk = 0; kk < 8; ++kk) {
            float a[8], b[8];
            *(float4*)(a)     = *(const float4*)&As[kk][ty * 8];
            *(float4*)(a + 4) = *(const float4*)&As[kk][ty * 8 + 4];
            *(float4*)(b)     = *(const float4*)&Ws[kk][tx * 8];
            *(float4*)(b + 4) = *(const float4*)&Ws[kk][tx * 8 + 4];
#pragma unroll
            for (int i = 0; i < 8; ++i)
#pragma unroll
                for (int j = 0; j < 8; ++j) acc[i][j] = fmaf(a[i], b[j], acc[i][j]);
        }
    }
    float bj[8];
#pragma unroll
    for (int j = 0; j < 8; ++j) bj[j] = bias[n0 + tx * 8 + j];
#pragma unroll
    for (int i = 0; i < 8; ++i) {
        int row = m0 + ty * 8 + i;
        size_t base = (size_t)row * N + n0 + tx * 8;
        float vout[8];
#pragma unroll
        for (int j = 0; j < 8; ++j) {
            float vv = acc[i][j] + bj[j];
            if (RES) vv += Rsrc[base + j];
            if (RELU) vv = fmaxf(vv, 0.f);
            vout[j] = vv;
        }
        *(float4*)&C[base]     = *(const float4*)(vout);
        *(float4*)&C[base + 4] = *(const float4*)(vout + 4);
    }
}

/* ---------------- attention ---------------- */
__global__ void scores_kernel(const float* __restrict__ q, const float* __restrict__ k,
                              const float* __restrict__ bias, float* __restrict__ sc) {
    int idx = blockIdx.x * 256 + threadIdx.x;     /* < 336*8*64*64 */
    int s = idx & 63;
    int l = (idx >> 6) & 63;
    int hh = (idx >> 12) & 7;
    int bm = idx >> 15;
    const float* qp = q + ((size_t)(bm * 64 + l)) * DD + hh * EE;
    const float* kp = k + ((size_t)(bm * 64 + s)) * DD + hh * EE;
    float acc = 0.f;
#pragma unroll 8
    for (int e = 0; e < EE; ++e) acc += qp[e] * kp[e];
    sc[idx] = acc * 0.10206207261596575f + bias[(l * 64 + s) * 8 + hh];
}

__global__ void softmax_kernel(float* __restrict__ sc) {
    int idx = blockIdx.x * 256 + threadIdx.x;     /* < 172032 rows */
    float* p = sc + (size_t)idx * 64;
    float mx = -1e30f;
#pragma unroll 8
    for (int s = 0; s < 64; ++s) mx = fmaxf(mx, p[s]);
    float sum = 0.f;
#pragma unroll 8
    for (int s = 0; s < 64; ++s) { float e = expf(p[s] - mx); p[s] = e; sum += e; }
    float inv = 1.f / sum;
#pragma unroll 8
    for (int s = 0; s < 64; ++s) p[s] *= inv;
}

__global__ void av_kernel(const float* __restrict__ sc, const float* __restrict__ v,
                          float* __restrict__ o) {
    int idx = blockIdx.x * 256 + threadIdx.x;     /* < ROWS*DD */
    int bm = idx / (NN * DD);
    int rem = idx - bm * (NN * DD);
    int l = rem / DD;
    int d = rem - l * DD;
    int hh = d / EE;
    const float* pp = sc + (((size_t)(bm * 8 + hh) * 64) + l) * 64;
    const float* vp = v + (size_t)bm * (NN * DD) + d;
    float acc = 0.f;
#pragma unroll 8
    for (int s = 0; s < 64; ++s) acc += pp[s] * vp[(size_t)s * DD];
    o[idx] = acc;
}

/* ---------------- batchnorm over tokens ---------------- */
__global__ void zero_kernel(float* __restrict__ p, int n) {
    int idx = blockIdx.x * 256 + threadIdx.x;
    if (idx < n) p[idx] = 0.f;
}

__global__ void bn_reduce_kernel(const float* __restrict__ X, float* __restrict__ sum,
                                 float* __restrict__ sq) {
    int r0 = blockIdx.x * 128;
    float s[3] = {0.f, 0.f, 0.f}, q[3] = {0.f, 0.f, 0.f};
    for (int r = 0; r < 128; ++r) {
        const float* xp = X + (size_t)(r0 + r) * DD;
#pragma unroll
        for (int j = 0; j < 3; ++j) {
            float v = xp[threadIdx.x + j * 256];
            s[j] += v; q[j] += v * v;
        }
    }
#pragma unroll
    for (int j = 0; j < 3; ++j) {
        atomicAdd(&sum[threadIdx.x + j * 256], s[j]);
        atomicAdd(&sq[threadIdx.x + j * 256], q[j]);
    }
}

__global__ void bn_apply_kernel(float* __restrict__ X, const float* __restrict__ sum,
                                const float* __restrict__ sq, const float* __restrict__ g,
                                const float* __restrict__ be) {
    int idx = blockIdx.x * 256 + threadIdx.x;
    int c = idx % DD;
    const float inv_n = 1.f / (float)ROWS;
    float mean = sum[c] * inv_n;
    float var = sq[c] * inv_n - mean * mean;
    X[idx] = (X[idx] - mean) * rsqrtf(var + EPSF) * g[c] + be[c];
}

/* ---------------- final projection (336 x 96, K=49152) split-K ---------------- */
__global__ void final_gemm_kernel(const float* __restrict__ hbuf, const float* __restrict__ ow,
                                  float* __restrict__ osmall) {
    __shared__ float hs[8 * 1024];
    int row0 = blockIdx.x * 8;      /* 42 groups */
    int k0 = blockIdx.y * 1024;     /* 48 chunks */
    for (int j = threadIdx.x; j < 2048; j += 128) {
        int r = j >> 8, kq = j & 255;
        *(float4*)&hs[r * 1024 + kq * 4] =
            *(const float4*)&hbuf[(size_t)(row0 + r) * 49152 + k0 + kq * 4];
    }
    __syncthreads();
    int p = threadIdx.x;
    if (p < PREDN) {
        float acc[8] = {0.f, 0.f, 0.f, 0.f, 0.f, 0.f, 0.f, 0.f};
        const float* wp = ow + (size_t)p * 49152 + k0;
        for (int kq = 0; kq < 256; ++kq) {
            float4 w4 = *(const float4*)(wp + kq * 4);
#pragma unroll
            for (int r = 0; r < 8; ++r) {
                const float* hr = &hs[r * 1024 + kq * 4];
                acc[r] += hr[0] * w4.x + hr[1] * w4.y + hr[2] * w4.z + hr[3] * w4.w;
            }
        }
#pragma unroll
        for (int r = 0; r < 8; ++r) atomicAdd(&osmall[(row0 + r) * PREDN + p], acc[r]);
    }
}

/* ---------------- de-norm + output transpose ---------------- */
__global__ void denorm_kernel(const float* __restrict__ osmall, const float* __restrict__ outb,
                              const float* __restrict__ rw, const float* __restrict__ rb,
                              const float* __restrict__ mean, const float* __restrict__ stdv,
                              float* __restrict__ out) {
    int idx = blockIdx.x * 256 + threadIdx.x;     /* < 32256 ; (b, pred, m) */
    int m = idx % MM;
    int pr = (idx / MM) % PREDN;
    int b = idx / (MM * PREDN);
    int bm = b * MM + m;
    float v = osmall[bm * PREDN + pr] + outb[pr];
    v = (v - rb[m]) / (rw[m] + 1e-10f);
    out[idx] = v * stdv[bm] + mean[bm];
}

/* ---------------- launcher ---------------- */
extern "C" void kernel_launch(void* const* d_in, const int* in_sizes, int n_in,
                              void* d_out, int out_size) {
    const float* x         = (const float*)d_in[0];
    const float* attn_bias = (const float*)d_in[1];
    const float* revin_w   = (const float*)d_in[2];
    const float* revin_b   = (const float*)d_in[3];
    const float* in_w      = (const float*)d_in[4];
    const float* in_b      = (const float*)d_in[5];
    const float* ln1_g     = (const float*)d_in[6];
    const float* ln1_b     = (const float*)d_in[7];
    const float* spect_wr  = (const float*)d_in[8];
    const float* spect_wi  = (const float*)d_in[9];
    const float* Wq        = (const float*)d_in[10];
    const float* bq        = (const float*)d_in[11];
    const float* Wk        = (const float*)d_in[12];
    const float* bk        = (const float*)d_in[13];
    const float* Wv        = (const float*)d_in[14];
    const float* bv        = (const float*)d_in[15];
    const float* Wo        = (const float*)d_in[16];
    const float* bo        = (const float*)d_in[17];
    const float* c1_w      = (const float*)d_in[18];
    const float* c1_b      = (const float*)d_in[19];
    const float* c2_w      = (const float*)d_in[20];
    const float* c2_b      = (const float*)d_in[21];
    const float* bn1_g     = (const float*)d_in[22];
    const float* bn1_b     = (const float*)d_in[23];
    const float* bn2_g     = (const float*)d_in[24];
    const float* bn2_b     = (const float*)d_in[25];
    const float* norm_g    = (const float*)d_in[26];
    const float* norm_b    = (const float*)d_in[27];
    const float* out_w     = (const float*)d_in[28];
    const float* out_b     = (const float*)d_in[29];

    float* base = nullptr;
    cudaGetSymbolAddress((void**)&base, g_buf);
    float* mean   = base + OFF_MEAN;
    float* stdv   = base + OFF_STD;
    float* patch  = base + OFF_PATCH;
    float* Tm     = base + OFF_T;
    float* mu     = base + OFF_MU;
    float* rv     = base + OFF_RV;
    float* ad     = base + OFF_AD;
    float* bnsum  = base + OFF_BNSUM;
    float* bnsq   = base + OFF_BNSQ;
    float* osmall = base + OFF_OSMALL;
    float* h      = base + OFF_H;
    float* y      = base + OFF_Y;
    float* q      = base + OFF_Q;
    float* k      = base + OFF_K;
    float* v      = base + OFF_V;
    float* o      = base + OFF_O;
    float* sc     = base + OFF_SC;
    float* f4     = base + OFF_F4;

    const int TPB = 256;
    const int G_ED = (ROWS * DD) / TPB;      /* 64512 */

    revin_stats_kernel<<<BMC, TPB>>>(x, mean, stdv);
    patches_kernel<<<344064 / TPB, TPB>>>(x, mean, stdv, revin_w, revin_b, patch);
    computeT_kernel<<<NLAYER, TPB>>>(spect_wr, spect_wi, Tm);
    embed0_kernel<<<G_ED, TPB>>>(patch, in_w, in_b, h);

    dim3 gP(DD / 128, ROWS / 128);           /* (6,168) */
    dim3 gF1(FF4 / 128, ROWS / 128);         /* (24,168) */

    for (int i = 0; i < NLAYER; ++i) {
        pn_stats_kernel<<<16384 / TPB, TPB>>>(patch, mu, rv);
        spect_kernel<<<344064 / TPB, TPB>>>(patch, mu, rv, ln1_g + i * MM, ln1_b + i * MM,
                                            Tm + i * 4096, ad);
        embed_add_kernel<<<G_ED, TPB>>>(h, ad, in_w, in_b, y);

        sgemm_kernel<0, 0><<<gP, TPB>>>(y, Wq + (size_t)i * DD * DD, bq + i * DD, nullptr, q, ROWS, DD, DD);
        sgemm_kernel<0, 0><<<gP, TPB>>>(y, Wk + (size_t)i * DD * DD, bk + i * DD, nullptr, k, ROWS, DD, DD);
        sgemm_kernel<0, 0><<<gP, TPB>>>(y, Wv + (size_t)i * DD * DD, bv + i * DD, nullptr, v, ROWS, DD, DD);

        scores_kernel<<<11010048 / TPB, TPB>>>(q, k, attn_bias, sc);
        softmax_kernel<<<172032 / TPB, TPB>>>(sc);
        av_kernel<<<G_ED, TPB>>>(sc, v, o);

        sgemm_kernel<0, 1><<<gP, TPB>>>(o, Wo + (size_t)i * DD * DD, bo + i * DD, y, y, ROWS, DD, DD);

        zero_kernel<<<6, TPB>>>(bnsum, 1536);     /* bnsum+bnsq contiguous */
        bn_reduce_kernel<<<ROWS / 128, TPB>>>(y, bnsum, bnsq);
        bn_apply_kernel<<<G_ED, TPB>>>(y, bnsum, bnsq, bn1_g + i * DD, bn1_b + i * DD);

        sgemm_kernel<1, 0><<<gF1, TPB>>>(y, c1_w + (size_t)i * FF4 * DD, c1_b + i * FF4, nullptr, f4, ROWS, FF4, DD);
        sgemm_kernel<0, 1><<<gP, TPB>>>(f4, c2_w + (size_t)i * DD * FF4, c2_b + i * DD, y, h, ROWS, DD, FF4);

        zero_kernel<<<6, TPB>>>(bnsum, 1536);
        bn_reduce_kernel<<<ROWS / 128, TPB>>>(h, bnsum, bnsq);
        bn_apply_kernel<<<G_ED, TPB>>>(h, bnsum, bnsq, bn2_g + i * DD, bn2_b + i * DD);
    }

    zero_kernel<<<6, TPB>>>(bnsum, 1536);
    bn_reduce_kernel<<<ROWS / 128, TPB>>>(h, bnsum, bnsq);
    bn_apply_kernel<<<G_ED, TPB>>>(h, bnsum, bnsq, norm_g, norm_b);

    zero_kernel<<<32256 / TPB, TPB>>>(osmall, 32256);
    final_gemm_kernel<<<dim3(BMC / 8, 48), 128>>>(h, out_w, osmall);
    denorm_kernel<<<32256 / TPB, TPB>>>(osmall, out_b, revin_w, revin_b, mean, stdv,
                                        (float*)d_out);
}

// round 2
// speedup vs baseline: 2.7813x; 2.7813x over previous
#include <cuda_runtime.h>
#include <math.h>
#include <stdint.h>

#define BB 16
#define LL 1024
#define MM 21
#define PP 16
#define NN 64
#define DD 768
#define HH 8
#define EE 96
#define FF4 3072
#define NLAYER 3
#define FREQ 33
#define A2 32
#define PREDN 96
#define BMC (BB*MM)          /* 336 */
#define ROWS (BMC*NN)        /* 21504 */
#define EPSF 1e-5f

/* ---------------- scratch layout (floats) ---------------- */
#define OFF_MEAN   0u
#define OFF_STD    512u
#define OFF_PATCH  1024u
#define OFF_T      345088u
#define OFF_MU     357376u
#define OFF_RV     373760u
#define OFF_AD     390144u
#define OFF_BNSUM  734208u
#define OFF_BNSQ   734976u
#define OFF_OSMALL 735744u
#define OFF_H      768000u
#define OFF_Y      (OFF_H + 16515072u)
#define OFF_Q      (OFF_Y + 16515072u)
#define OFF_K      (OFF_Q + 16515072u)
#define OFF_V      (OFF_K + 16515072u)
#define OFF_O      (OFF_V + 16515072u)
#define OFF_SC     (OFF_O + 16515072u)
#define OFF_F4     (OFF_SC + 11010048u)
#define TOTAL_F    (OFF_F4 + 66060288u)

__device__ float g_buf[TOTAL_F];

/* ---------------- RevIN stats ---------------- */
__global__ void revin_stats_kernel(const float* __restrict__ x, float* __restrict__ mean,
                                   float* __restrict__ stdv) {
    int bm = blockIdx.x;
    int b = bm / MM, m = bm % MM;
    const float* xp = x + (size_t)b * LL * MM + m;
    float s = 0.f, s2 = 0.f;
    for (int l = threadIdx.x; l < LL; l += 256) {
        float v = xp[(size_t)l * MM];
        s += v; s2 += v * v;
    }
    __shared__ float sh0[256], sh1[256];
    sh0[threadIdx.x] = s; sh1[threadIdx.x] = s2;
    __syncthreads();
    for (int off = 128; off > 0; off >>= 1) {
        if (threadIdx.x < off) { sh0[threadIdx.x] += sh0[threadIdx.x + off]; sh1[threadIdx.x] += sh1[threadIdx.x + off]; }
        __syncthreads();
    }
    if (threadIdx.x == 0) {
        float mu = sh0[0] * (1.f / LL);
        float var = sh1[0] * (1.f / LL) - mu * mu;
        mean[bm] = mu;
        stdv[bm] = sqrtf(var + EPSF);
    }
}

/* ---------------- patches (RevIN applied) ---------------- */
__global__ void patches_kernel(const float* __restrict__ x, const float* __restrict__ mean,
                               const float* __restrict__ stdv, const float* __restrict__ rw,
                               const float* __restrict__ rb, float* __restrict__ patches) {
    int idx = blockIdx.x * 256 + threadIdx.x;
    int p = idx & 15;
    int n = (idx >> 4) & 63;
    int bm = idx >> 10;
    int m = bm % MM;
    int b = bm / MM;
    int l = n * 16 + p;
    float v = x[(size_t)b * LL * MM + (size_t)l * MM + m];
    v = (v - mean[bm]) / stdv[bm] * rw[m] + rb[m];
    patches[idx] = v;
}

/* ---------------- composed spectral transform T ---------------- */
__global__ void computeT_kernel(const float* __restrict__ wr, const float* __restrict__ wi,
                                float* __restrict__ T) {
    int lay = blockIdx.x;
    __shared__ float Ur[32][64], Ui[32][64];
    const float* wrp = wr + (size_t)lay * FREQ * A2;
    const float* wip = wi + (size_t)lay * FREQ * A2;
    const float c0 = 6.28318530717958647692f / 64.f;
    for (int e = threadIdx.x; e < 32 * 64; e += 256) {
        int d = e >> 6, n = e & 63;
        float sr = 0.f, si = 0.f;
        for (int kf = 0; kf < FREQ; ++kf) {
            float ang = c0 * (float)(kf * n);
            float cv, sv;
            sincosf(ang, &sv, &cv);
            sr += wrp[kf * A2 + d] * cv;
            si += wip[kf * A2 + d] * (-sv);
        }
        Ur[d][n] = sr; Ui[d][n] = si;
    }
    __syncthreads();
    for (int e = threadIdx.x; e < 64 * 64; e += 256) {
        int a = e >> 6, n = e & 63;
        float tval = Ur[0][n];
        for (int d = 1; d < 32; ++d) {
            float ang = c0 * (float)(d * a);
            float cv, sv;
            sincosf(ang, &sv, &cv);
            tval += 2.f * (Ur[d][n] * cv - Ui[d][n] * sv);
        }
        T[lay * 4096 + e] = tval * (1.f / 64.f);
    }
}

/* ---------------- instance-norm stats over M ---------------- */
__global__ void pn_stats_kernel(const float* __restrict__ patches, float* __restrict__ mu,
                                float* __restrict__ rv) {
    int idx = blockIdx.x * 256 + threadIdx.x;
    int b = idx >> 10;
    int np = idx & 1023;
    const float* pp = patches + (size_t)b * 21504 + np;
    float s = 0.f, s2 = 0.f;
#pragma unroll
    for (int m = 0; m < MM; ++m) { float v = pp[m * 1024]; s += v; s2 += v * v; }
    float m0 = s * (1.f / MM);
    float var = s2 * (1.f / MM) - m0 * m0;
    mu[idx] = m0;
    rv[idx] = rsqrtf(var + EPSF);
}

/* ---------------- spectral mixing ---------------- */
__global__ void spect_kernel(const float* __restrict__ patches, const float* __restrict__ mu,
                             const float* __restrict__ rv, const float* __restrict__ g,
                             const float* __restrict__ be, const float* __restrict__ T,
                             float* __restrict__ ad) {
    int idx = blockIdx.x * 256 + threadIdx.x;
    int p = idx & 15;
    int a = (idx >> 4) & 63;
    int bm = idx >> 10;
    int m = bm % MM;
    int b = bm / MM;
    float gm = g[m], bm_ = be[m];
    const float* pp  = patches + (size_t)bm * 1024 + p;
    const float* mup = mu + b * 1024 + p;
    const float* rvp = rv + b * 1024 + p;
    const float* Tp  = T + a * 64;
    float acc = 0.f;
#pragma unroll 8
    for (int n = 0; n < 64; ++n) {
        float pn = (pp[n * 16] - mup[n * 16]) * rvp[n * 16] * gm + bm_;
        acc += Tp[n] * pn;
    }
    ad[idx] = acc;
}

/* ---------------- embeddings: out = [Hin +] src16 @ in_w.T + in_b ---------------- */
template<int ADD>
__global__ __launch_bounds__(256) void embed_kernel(const float* __restrict__ src,
                                                    const float* __restrict__ Hin,
                                                    const float* __restrict__ inw,
                                                    const float* __restrict__ inb,
                                                    float* __restrict__ out) {
    __shared__ float ps[1024];
    int blk = blockIdx.x;
    int t = threadIdx.x;
    const float4* sp = (const float4*)(src + (size_t)blk * 1024);
    ((float4*)ps)[t] = sp[t];
    float w[3][16], bb[3];
#pragma unroll
    for (int j = 0; j < 3; ++j) {
        int c = t + 256 * j;
        bb[j] = inb[c];
#pragma unroll
        for (int p4 = 0; p4 < 4; ++p4) {
            float4 wv = *(const float4*)(inw + (size_t)c * 16 + p4 * 4);
            w[j][p4 * 4] = wv.x; w[j][p4 * 4 + 1] = wv.y; w[j][p4 * 4 + 2] = wv.z; w[j][p4 * 4 + 3] = wv.w;
        }
    }
    __syncthreads();
    size_t rowbase = (size_t)blk * 64 * DD;
    for (int r = 0; r < 64; ++r) {
        float pr[16];
#pragma unroll
        for (int p4 = 0; p4 < 4; ++p4) {
            float4 pv = *(const float4*)&ps[r * 16 + p4 * 4];
            pr[p4 * 4] = pv.x; pr[p4 * 4 + 1] = pv.y; pr[p4 * 4 + 2] = pv.z; pr[p4 * 4 + 3] = pv.w;
        }
        size_t ro = rowbase + (size_t)r * DD;
#pragma unroll
        for (int j = 0; j < 3; ++j) {
            float acc = bb[j];
            if (ADD) acc += Hin[ro + t + 256 * j];
#pragma unroll
            for (int p = 0; p < 16; ++p) acc = fmaf(pr[p], w[j][p], acc);
            out[ro + t + 256 * j] = acc;
        }
    }
}

/* ---------------- TF32 tensor-core GEMM: C = A(MxK) @ W^T(NxK) + bias [+R][relu] ------- */
__device__ __forceinline__ float to_tf32(float x) {
    unsigned u;
    asm("cvt.rna.tf32.f32 %0, %1;" : "=r"(u) : "f"(x));
    return __uint_as_float(u);
}
__device__ __forceinline__ void mma_tf32(float* d, const unsigned* a, const unsigned* b) {
    asm volatile("mma.sync.aligned.m16n8k8.row.col.f32.tf32.tf32.f32 "
                 "{%0,%1,%2,%3},{%4,%5,%6,%7},{%8,%9},{%0,%1,%2,%3};"
                 : "+f"(d[0]), "+f"(d[1]), "+f"(d[2]), "+f"(d[3])
                 : "r"(a[0]), "r"(a[1]), "r"(a[2]), "r"(a[3]), "r"(b[0]), "r"(b[1]));
}

template<int RELU, int RES>
__global__ __launch_bounds__(256) void mma_gemm(const float* __restrict__ A,
                                                const float* __restrict__ W,
                                                const float* __restrict__ bias,
                                                const float* __restrict__ Rsrc,
                                                float* __restrict__ C,
                                                int M, int N, int K) {
    __shared__ float As[2][128 * 20];
    __shared__ float Bs[2][64 * 20];
    const int t = threadIdx.x;
    const int wid = t >> 5, lane = t & 31;
    const int wm = wid & 3, wn = wid >> 2;          /* 4x2 warps, each 32x32 */
    const int m0 = blockIdx.y * 128, n0 = blockIdx.x * 64;
    const int arow = t >> 1, acol = (t & 1) * 8;
    const int brow = t >> 2, bcol = (t & 3) * 4;
    const float* Agp = A + (size_t)(m0 + arow) * K + acol;
    const float* Bgp = W + (size_t)(n0 + brow) * K + bcol;

    float acc[2][4][4];
#pragma unroll
    for (int i = 0; i < 2; ++i)
#pragma unroll
        for (int j = 0; j < 4; ++j)
#pragma unroll
            for (int r = 0; r < 4; ++r) acc[i][j][r] = 0.f;

    float4 pa0 = *(const float4*)(Agp);
    float4 pa1 = *(const float4*)(Agp + 4);
    float4 pb  = *(const float4*)(Bgp);
    {
        float* d = &As[0][arow * 20 + acol];
        d[0] = to_tf32(pa0.x); d[1] = to_tf32(pa0.y); d[2] = to_tf32(pa0.z); d[3] = to_tf32(pa0.w);
        d[4] = to_tf32(pa1.x); d[5] = to_tf32(pa1.y); d[6] = to_tf32(pa1.z); d[7] = to_tf32(pa1.w);
        float* e = &Bs[0][brow * 20 + bcol];
        e[0] = to_tf32(pb.x); e[1] = to_tf32(pb.y); e[2] = to_tf32(pb.z); e[3] = to_tf32(pb.w);
    }
    __syncthreads();

    const int NT = K >> 4;
    int buf = 0;
    const int fr = lane >> 2, fc = lane & 3;
    for (int kb = 0; kb < NT; ++kb) {
        if (kb + 1 < NT) {
            const float* Ag2 = Agp + (kb + 1) * 16;
            const float* Bg2 = Bgp + (kb + 1) * 16;
            pa0 = *(const float4*)(Ag2);
            pa1 = *(const float4*)(Ag2 + 4);
            pb  = *(const float4*)(Bg2);
        }
        const float* Ab = As[buf];
        const float* Bb = Bs[buf];
#pragma unroll
        for (int ks = 0; ks < 2; ++ks) {
            const int k0 = ks * 8;
            unsigned af[2][4], bf[4][2];
#pragma unroll
            for (int mt = 0; mt < 2; ++mt) {
                int row = wm * 32 + mt * 16 + fr;
                af[mt][0] = __float_as_uint(Ab[row * 20 + k0 + fc]);
                af[mt][1] = __float_as_uint(Ab[(row + 8) * 20 + k0 + fc]);
                af[mt][2] = __float_as_uint(Ab[row * 20 + k0 + fc + 4]);
                af[mt][3] = __float_as_uint(Ab[(row + 8) * 20 + k0 + fc + 4]);
            }
#pragma unroll
            for (int nt = 0; nt < 4; ++nt) {
                int col = wn * 32 + nt * 8 + fr;
                bf[nt][0] = __float_as_uint(Bb[col * 20 + k0 + fc]);
                bf[nt][1] = __float_as_uint(Bb[col * 20 + k0 + fc + 4]);
            }
#pragma unroll
            for (int mt = 0; mt < 2; ++mt)
#pragma unroll
                for (int nt = 0; nt < 4; ++nt)
                    mma_tf32(acc[mt][nt], af[mt], bf[nt]);
        }
        if (kb + 1 < NT) {
            float* d = &As[buf ^ 1][arow * 20 + acol];
            d[0] = to_tf32(pa0.x); d[1] = to_tf32(pa0.y); d[2] = to_tf32(pa0.z); d[3] = to_tf32(pa0.w);
            d[4] = to_tf32(pa1.x); d[5] = to_tf32(pa1.y); d[6] = to_tf32(pa1.z); d[7] = to_tf32(pa1.w);
            float* e = &Bs[buf ^ 1][brow * 20 + bcol];
            e[0] = to_tf32(pb.x); e[1] = to_tf32(pb.y); e[2] = to_tf32(pb.z); e[3] = to_tf32(pb.w);
            __syncthreads();
            buf ^= 1;
        }
    }

    const int c2 = (lane & 3) * 2;
#pragma unroll
    for (int mt = 0; mt < 2; ++mt) {
        int row = m0 + wm * 32 + mt * 16 + fr;
#pragma unroll
        for (int nt = 0; nt < 4; ++nt) {
            int col = n0 + wn * 32 + nt * 8 + c2;
            size_t i0 = (size_t)row * N + col;
            size_t i1 = (size_t)(row + 8) * N + col;
            float b0 = bias[col], b1 = bias[col + 1];
            float v0 = acc[mt][nt][0] + b0, v1 = acc[mt][nt][1] + b1;
            float v2 = acc[mt][nt][2] + b0, v3 = acc[mt][nt][3] + b1;
            if (RES) {
                float2 r0 = *(const float2*)&Rsrc[i0];
                float2 r1 = *(const float2*)&Rsrc[i1];
                v0 += r0.x; v1 += r0.y; v2 += r1.x; v3 += r1.y;
            }
            if (RELU) { v0 = fmaxf(v0, 0.f); v1 = fmaxf(v1, 0.f); v2 = fmaxf(v2, 0.f); v3 = fmaxf(v3, 0.f); }
            float2 o0 = {v0, v1}, o1 = {v2, v3};
            *(float2*)&C[i0] = o0;
            *(float2*)&C[i1] = o1;
        }
    }
}

/* ---------------- attention: tiled scores ---------------- */
__global__ __launch_bounds__(256) void scores_tile_kernel(const float* __restrict__ q,
                                                          const float* __restrict__ k,
                                                          const float* __restrict__ bias,
                                                          float* __restrict__ sc) {
    int bm = blockIdx.x, h = blockIdx.y, sh = blockIdx.z;
    __shared__ float qs[64 * 96];
    __shared__ float ksT[96 * 33];
    int t = threadIdx.x;
    const float* qg = q + (size_t)bm * 64 * DD + h * EE;
    const float* kg = k + (size_t)bm * 64 * DD + h * EE + (size_t)sh * 32 * DD;
    for (int i = t; i < 1536; i += 256) {
        int r = i / 24, c = i % 24;
        ((float4*)qs)[r * 24 + c] = *(const float4*)(qg + (size_t)r * DD + c * 4);
    }
    for (int i = t; i < 768; i += 256) {
        int s = i / 24, c = i % 24;
        float4 v4 = *(const float4*)(kg + (size_t)s * DD + c * 4);
        ksT[(c * 4 + 0) * 33 + s] = v4.x;
        ksT[(c * 4 + 1) * 33 + s] = v4.y;
        ksT[(c * 4 + 2) * 33 + s] = v4.z;
        ksT[(c * 4 + 3) * 33 + s] = v4.w;
    }
    __syncthreads();
    int l0 = (t >> 4) * 4, s0 = (t & 15) * 2;
    float acc[4][2] = {};
    for (int e = 0; e < 96; ++e) {
        float kv0 = ksT[e * 33 + s0], kv1 = ksT[e * 33 + s0 + 1];
#pragma unroll
        for (int i2 = 0; i2 < 4; ++i2) {
            float qv = qs[(l0 + i2) * 96 + e];
            acc[i2][0] = fmaf(qv, kv0, acc[i2][0]);
            acc[i2][1] = fmaf(qv, kv1, acc[i2][1]);
        }
    }
    const float SCALE = 0.10206207261596575f;
    float* scp = sc + (size_t)(bm * 8 + h) * 4096;
#pragma unroll
    for (int i2 = 0; i2 < 4; ++i2)
#pragma unroll
        for (int j = 0; j < 2; ++j) {
            int l = l0 + i2, s = sh * 32 + s0 + j;
            scp[l * 64 + s] = acc[i2][j] * SCALE + bias[(l * 64 + s) * 8 + h];
        }
}

__global__ void softmax_kernel(float* __restrict__ sc) {
    int idx = blockIdx.x * 256 + threadIdx.x;
    float* p = sc + (size_t)idx * 64;
    float mx = -1e30f;
#pragma unroll 8
    for (int s = 0; s < 64; ++s) mx = fmaxf(mx, p[s]);
    float sum = 0.f;
#pragma unroll 8
    for (int s = 0; s < 64; ++s) { float e = expf(p[s] - mx); p[s] = e; sum += e; }
    float inv = 1.f / sum;
#pragma unroll 8
    for (int s = 0; s < 64; ++s) p[s] *= inv;
}

/* ---------------- attention: tiled AV ---------------- */
__global__ __launch_bounds__(256) void av_tile_kernel(const float* __restrict__ sc,
                                                      const float* __restrict__ v,
                                                      float* __restrict__ o) {
    int bm = blockIdx.x, h = blockIdx.y;
    __shared__ float at[64 * 65];
    __shared__ float vs[64 * 96];
    int t = threadIdx.x;
    const float* ap = sc + (size_t)(bm * 8 + h) * 4096;
    const float* vg = v + (size_t)bm * 64 * DD + h * EE;
    for (int i = t; i < 1024; i += 256) {
        int l = i >> 4, c = i & 15;
        float4 a4 = *(const float4*)(ap + l * 64 + c * 4);
        at[l * 65 + c * 4 + 0] = a4.x; at[l * 65 + c * 4 + 1] = a4.y;
        at[l * 65 + c * 4 + 2] = a4.z; at[l * 65 + c * 4 + 3] = a4.w;
    }
    for (int i = t; i < 1536; i += 256) {
        int s = i / 24, c = i % 24;
        *(float4*)&vs[s * 96 + c * 4] = *(const float4*)(vg + (size_t)s * DD + c * 4);
    }
    __syncthreads();
    int l0 = (t >> 4) * 4, e0 = (t & 15) * 6;
    float acc[4][6] = {};
    for (int s = 0; s < 64; ++s) {
        float av_[4], vv[6];
#pragma unroll
        for (int i2 = 0; i2 < 4; ++i2) av_[i2] = at[(l0 + i2) * 65 + s];
#pragma unroll
        for (int j = 0; j < 6; ++j) vv[j] = vs[s * 96 + e0 + j];
#pragma unroll
        for (int i2 = 0; i2 < 4; ++i2)
#pragma unroll
            for (int j = 0; j < 6; ++j) acc[i2][j] = fmaf(av_[i2], vv[j], acc[i2][j]);
    }
    float* op = o + (size_t)bm * 64 * DD + h * EE;
#pragma unroll
    for (int i2 = 0; i2 < 4; ++i2)
#pragma unroll
        for (int j = 0; j < 6; ++j)
            op[(size_t)(l0 + i2) * DD + e0 + j] = acc[i2][j];
}

/* ---------------- batchnorm ---------------- */
__global__ void zero_kernel(float* __restrict__ p, int n) {
    int idx = blockIdx.x * 256 + threadIdx.x;
    if (idx < n) p[idx] = 0.f;
}

__global__ void bn_reduce_kernel(const float* __restrict__ X, float* __restrict__ sum,
                                 float* __restrict__ sq) {
    int r0 = blockIdx.x * 128;
    float s[3] = {0.f, 0.f, 0.f}, q[3] = {0.f, 0.f, 0.f};
    for (int r = 0; r < 128; ++r) {
        const float* xp = X + (size_t)(r0 + r) * DD;
#pragma unroll
        for (int j = 0; j < 3; ++j) {
            float v = xp[threadIdx.x + j * 256];
            s[j] += v; q[j] += v * v;
        }
    }
#pragma unroll
    for (int j = 0; j < 3; ++j) {
        atomicAdd(&sum[threadIdx.x + j * 256], s[j]);
        atomicAdd(&sq[threadIdx.x + j * 256], q[j]);
    }
}

__global__ void bn_apply_kernel(float* __restrict__ X, const float* __restrict__ sum,
                                const float* __restrict__ sq, const float* __restrict__ g,
                                const float* __restrict__ be) {
    int idx = blockIdx.x * 256 + threadIdx.x;
    int c = idx % DD;
    const float inv_n = 1.f / (float)ROWS;
    float mean = sum[c] * inv_n;
    float var = sq[c] * inv_n - mean * mean;
    X[idx] = (X[idx] - mean) * rsqrtf(var + EPSF) * g[c] + be[c];
}

/* ---------------- final projection ---------------- */
__global__ void final_gemm_kernel(const float* __restrict__ hbuf, const float* __restrict__ ow,
                                  float* __restrict__ osmall) {
    __shared__ float hs[8 * 1024];
    int row0 = blockIdx.x * 8;
    int k0 = blockIdx.y * 1024;
    for (int j = threadIdx.x; j < 2048; j += 128) {
        int r = j >> 8, kq = j & 255;
        *(float4*)&hs[r * 1024 + kq * 4] =
            *(const float4*)&hbuf[(size_t)(row0 + r) * 49152 + k0 + kq * 4];
    }
    __syncthreads();
    int p = threadIdx.x;
    if (p < PREDN) {
        float acc[8] = {0.f, 0.f, 0.f, 0.f, 0.f, 0.f, 0.f, 0.f};
        const float* wp = ow + (size_t)p * 49152 + k0;
        for (int kq = 0; kq < 256; ++kq) {
            float4 w4 = *(const float4*)(wp + kq * 4);
#pragma unroll
            for (int r = 0; r < 8; ++r) {
                const float* hr = &hs[r * 1024 + kq * 4];
                acc[r] += hr[0] * w4.x + hr[1] * w4.y + hr[2] * w4.z + hr[3] * w4.w;
            }
        }
#pragma unroll
        for (int r = 0; r < 8; ++r) atomicAdd(&osmall[(row0 + r) * PREDN + p], acc[r]);
    }
}

/* ---------------- de-norm + output transpose ---------------- */
__global__ void denorm_kernel(const float* __restrict__ osmall, const float* __restrict__ outb,
                              const float* __restrict__ rw, const float* __restrict__ rb,
                              const float* __restrict__ mean, const float* __restrict__ stdv,
                              float* __restrict__ out) {
    int idx = blockIdx.x * 256 + threadIdx.x;
    int m = idx % MM;
    int pr = (idx / MM) % PREDN;
    int b = idx / (MM * PREDN);
    int bm = b * MM + m;
    float v = osmall[bm * PREDN + pr] + outb[pr];
    v = (v - rb[m]) / (rw[m] + 1e-10f);
    out[idx] = v * stdv[bm] + mean[bm];
}

/* ---------------- launcher ---------------- */
extern "C" void kernel_launch(void* const* d_in, const int* in_sizes, int n_in,
                              void* d_out, int out_size) {
    const float* x         = (const float*)d_in[0];
    const float* attn_bias = (const float*)d_in[1];
    const float* revin_w   = (const float*)d_in[2];
    const float* revin_b   = (const float*)d_in[3];
    const float* in_w      = (const float*)d_in[4];
    const float* in_b      = (const float*)d_in[5];
    const float* ln1_g     = (const float*)d_in[6];
    const float* ln1_b     = (const float*)d_in[7];
    const float* spect_wr  = (const float*)d_in[8];
    const float* spect_wi  = (const float*)d_in[9];
    const float* Wq        = (const float*)d_in[10];
    const float* bq        = (const float*)d_in[11];
    const float* Wk        = (const float*)d_in[12];
    const float* bk        = (const float*)d_in[13];
    const float* Wv        = (const float*)d_in[14];
    const float* bv        = (const float*)d_in[15];
    const float* Wo        = (const float*)d_in[16];
    const float* bo        = (const float*)d_in[17];
    const float* c1_w      = (const float*)d_in[18];
    const float* c1_b      = (const float*)d_in[19];
    const float* c2_w      = (const float*)d_in[20];
    const float* c2_b      = (const float*)d_in[21];
    const float* bn1_g     = (const float*)d_in[22];
    const float* bn1_b     = (const float*)d_in[23];
    const float* bn2_g     = (const float*)d_in[24];
    const float* bn2_b     = (const float*)d_in[25];
    const float* norm_g    = (const float*)d_in[26];
    const float* norm_b    = (const float*)d_in[27];
    const float* out_w     = (const float*)d_in[28];
    const float* out_b     = (const float*)d_in[29];

    float* base = nullptr;
    cudaGetSymbolAddress((void**)&base, g_buf);
    float* mean   = base + OFF_MEAN;
    float* stdv   = base + OFF_STD;
    float* patch  = base + OFF_PATCH;
    float* Tm     = base + OFF_T;
    float* mu     = base + OFF_MU;
    float* rv     = base + OFF_RV;
    float* ad     = base + OFF_AD;
    float* bnsum  = base + OFF_BNSUM;
    float* bnsq   = base + OFF_BNSQ;
    float* osmall = base + OFF_OSMALL;
    float* h      = base + OFF_H;
    float* y      = base + OFF_Y;
    float* q      = base + OFF_Q;
    float* k      = base + OFF_K;
    float* v      = base + OFF_V;
    float* o      = base + OFF_O;
    float* sc     = base + OFF_SC;
    float* f4     = base + OFF_F4;

    const int TPB = 256;
    const int G_ED = (ROWS * DD) / TPB;

    revin_stats_kernel<<<BMC, TPB>>>(x, mean, stdv);
    patches_kernel<<<344064 / TPB, TPB>>>(x, mean, stdv, revin_w, revin_b, patch);
    computeT_kernel<<<NLAYER, TPB>>>(spect_wr, spect_wi, Tm);
    embed_kernel<0><<<BMC, TPB>>>(patch, nullptr, in_w, in_b, h);

    dim3 gP(DD / 64, ROWS / 128);            /* (12,168) */
    dim3 gF1(FF4 / 64, ROWS / 128);          /* (48,168) */
    dim3 gS(BMC, HH, 2);
    dim3 gAV(BMC, HH);

    for (int i = 0; i < NLAYER; ++i) {
        pn_stats_kernel<<<16384 / TPB, TPB>>>(patch, mu, rv);
        spect_kernel<<<344064 / TPB, TPB>>>(patch, mu, rv, ln1_g + i * MM, ln1_b + i * MM,
                                            Tm + i * 4096, ad);
        embed_kernel<1><<<BMC, TPB>>>(ad, h, in_w, in_b, y);

        mma_gemm<0, 0><<<gP, TPB>>>(y, Wq + (size_t)i * DD * DD, bq + i * DD, nullptr, q, ROWS, DD, DD);
        mma_gemm<0, 0><<<gP, TPB>>>(y, Wk + (size_t)i * DD * DD, bk + i * DD, nullptr, k, ROWS, DD, DD);
        mma_gemm<0, 0><<<gP, TPB>>>(y, Wv + (size_t)i * DD * DD, bv + i * DD, nullptr, v, ROWS, DD, DD);

        scores_tile_kernel<<<gS, TPB>>>(q, k, attn_bias, sc);
        softmax_kernel<<<172032 / TPB, TPB>>>(sc);
        av_tile_kernel<<<gAV, TPB>>>(sc, v, o);

        mma_gemm<0, 1><<<gP, TPB>>>(o, Wo + (size_t)i * DD * DD, bo + i * DD, y, y, ROWS, DD, DD);

        zero_kernel<<<6, TPB>>>(bnsum, 1536);
        bn_reduce_kernel<<<ROWS / 128, TPB>>>(y, bnsum, bnsq);
        bn_apply_kernel<<<G_ED, TPB>>>(y, bnsum, bnsq, bn1_g + i * DD, bn1_b + i * DD);

        mma_gemm<1, 0><<<gF1, TPB>>>(y, c1_w + (size_t)i * FF4 * DD, c1_b + i * FF4, nullptr, f4, ROWS, FF4, DD);
        mma_gemm<0, 1><<<gP, TPB>>>(f4, c2_w + (size_t)i * DD * FF4, c2_b + i * DD, y, h, ROWS, DD, FF4);

        zero_kernel<<<6, TPB>>>(bnsum, 1536);
        bn_reduce_kernel<<<ROWS / 128, TPB>>>(h, bnsum, bnsq);
        bn_apply_kernel<<<G_ED, TPB>>>(h, bnsum, bnsq, bn2_g + i * DD, bn2_b + i * DD);
    }

    zero_kernel<<<6, TPB>>>(bnsum, 1536);
    bn_reduce_kernel<<<ROWS / 128, TPB>>>(h, bnsum, bnsq);
    bn_apply_kernel<<<G_ED, TPB>>>(h, bnsum, bnsq, norm_g, norm_b);

    zero_kernel<<<32256 / TPB, TPB>>>(osmall, 32256);
    final_gemm_kernel<<<dim3(BMC / 8, 48), 128>>>(h, out_w, osmall);
    denorm_kernel<<<32256 / TPB, TPB>>>(osmall, out_b, revin_w, revin_b, mean, stdv,
                                        (float*)d_out);
}

// round 4
// speedup vs baseline: 3.8740x; 1.3929x over previous
#include <cuda_runtime.h>
#include <cuda_bf16.h>
#include <math.h>
#include <stdint.h>

#define BB 16
#define LL 1024
#define MM 21
#define PP 16
#define NN 64
#define DD 768
#define HH 8
#define EE 96
#define FF4 3072
#define NLAYER 3
#define FREQ 33
#define A2 32
#define PREDN 96
#define BMC (BB*MM)          /* 336 */
#define ROWS (BMC*NN)        /* 21504 */
#define EPSF 1e-5f

/* ---------------- scratch layout (floats) ---------------- */
#define OFF_MEAN   0u
#define OFF_STD    512u
#define OFF_PATCH  1024u
#define OFF_T      345088u
#define OFF_MU     357376u
#define OFF_RV     373760u
#define OFF_AD     390144u
#define OFF_BNSUM  734208u
#define OFF_BNSQ   734976u
#define OFF_OSMALL 735744u
#define OFF_H      768000u
#define OFF_Y      (OFF_H + 16515072u)
#define OFF_Q      (OFF_Y + 16515072u)
#define OFF_K      (OFF_Q + 16515072u)
#define OFF_V      (OFF_K + 16515072u)
#define OFF_O      (OFF_V + 16515072u)
#define OFF_SC     (OFF_O + 16515072u)
#define OFF_F4     (OFF_SC + 11010048u)
#define OFF_WCVT   (OFF_F4 + 66060288u)
/* WCVT: Wq(1769472) Wk Wv Wo c1(7077888) c2(7077888) = 21233664 */
#define TOTAL_F    (OFF_WCVT + 21233664u)

__device__ float g_buf[TOTAL_F];

/* ================= helpers ================= */
__device__ __forceinline__ uint32_t s2u(const void* p) {
    uint32_t a;
    asm("{ .reg .u64 t; cvta.to.shared.u64 t, %1; cvt.u32.u64 %0, t; }" : "=r"(a) : "l"(p));
    return a;
}
__device__ __forceinline__ float to_tf32(float x) {
    unsigned u;
    asm("cvt.rna.tf32.f32 %0, %1;" : "=r"(u) : "f"(x));
    return __uint_as_float(u);
}
__device__ __forceinline__ void mma_tf32(float* d, const unsigned* a, const unsigned* b) {
    asm volatile("mma.sync.aligned.m16n8k8.row.col.f32.tf32.tf32.f32 "
                 "{%0,%1,%2,%3},{%4,%5,%6,%7},{%8,%9},{%0,%1,%2,%3};"
                 : "+f"(d[0]), "+f"(d[1]), "+f"(d[2]), "+f"(d[3])
                 : "r"(a[0]), "r"(a[1]), "r"(a[2]), "r"(a[3]), "r"(b[0]), "r"(b[1]));
}
__device__ __forceinline__ void cp16(uint32_t saddr, const void* g) {
    asm volatile("cp.async.ca.shared.global [%0], [%1], 16;" :: "r"(saddr), "l"(g));
}

/* ---------------- weight tf32-rna conversion ---------------- */
__global__ void wconv_kernel(const float* __restrict__ in, float* __restrict__ out, int n) {
    int idx = blockIdx.x * 256 + threadIdx.x;
    if (idx < n) out[idx] = to_tf32(in[idx]);
}

/* =========== cp.async 4-stage tf32 mma GEMM ===========
   C[M,N] = A[M,K] @ W[N,K]^T + bias (+Rsrc)(relu)(round)
   CTA tile 128x128, 8 warps (2x4), warp tile 64x32, K-step 16. */
#define STAGES 4
#define STG_F  5120                       /* floats per stage (A 2560 + B 2560) */
#define GSM2   (STAGES * STG_F * 4)       /* 81920 bytes */

template<int RELU, int RES, int ROUND>
__global__ __launch_bounds__(256, 2) void mma_gemm2(const float* __restrict__ A,
                                                    const float* __restrict__ W,
                                                    const float* __restrict__ bias,
                                                    const float* __restrict__ Rsrc,
                                                    float* __restrict__ C,
                                                    int M, int N, int K) {
    extern __shared__ float smem[];
    const int t = threadIdx.x;
    const int wid = t >> 5, lane = t & 31;
    const int wm = wid >> 2, wn = wid & 3;     /* 2x4 warps, 64x32 each */
    const int m0 = blockIdx.y * 128, n0 = blockIdx.x * 128;
    const int fr = lane >> 2, fc = lane & 3;
    const uint32_t sbase = s2u(smem);

    const int id0 = t, id1 = t + 256;
    const int rowA0 = id0 >> 2, cA0 = (id0 & 3) << 2;
    const int rowA1 = id1 >> 2, cA1 = (id1 & 3) << 2;
    const float* Agp = A + (size_t)m0 * K;
    const float* Bgp = W + (size_t)n0 * K;

    float acc[4][4][4];
#pragma unroll
    for (int i = 0; i < 4; ++i)
#pragma unroll
        for (int j = 0; j < 4; ++j)
#pragma unroll
            for (int r = 0; r < 4; ++r) acc[i][j][r] = 0.f;

    const int NT = K >> 4;

    /* prologue: issue stages 0..2 */
#pragma unroll
    for (int s = 0; s < STAGES - 1; ++s) {
        uint32_t sa = sbase + (uint32_t)(s * STG_F) * 4u;
        const float* Ag = Agp + s * 16;
        const float* Bg = Bgp + s * 16;
        cp16(sa + (uint32_t)(rowA0 * 20 + cA0) * 4u, Ag + (size_t)rowA0 * K + cA0);
        cp16(sa + (uint32_t)(rowA1 * 20 + cA1) * 4u, Ag + (size_t)rowA1 * K + cA1);
        cp16(sa + (uint32_t)(2560 + rowA0 * 20 + cA0) * 4u, Bg + (size_t)rowA0 * K + cA0);
        cp16(sa + (uint32_t)(2560 + rowA1 * 20 + cA1) * 4u, Bg + (size_t)rowA1 * K + cA1);
        asm volatile("cp.async.commit_group;");
    }

    for (int kb = 0; kb < NT; ++kb) {
        asm volatile("cp.async.wait_group %0;" :: "n"(STAGES - 2));
        __syncthreads();
        /* issue stage kb+3 into buffer (kb-1)&3 */
        if (kb + STAGES - 1 < NT) {
            int ss = (kb + STAGES - 1) & (STAGES - 1);
            uint32_t sa = sbase + (uint32_t)(ss * STG_F) * 4u;
            const float* Ag = Agp + (kb + STAGES - 1) * 16;
            const float* Bg = Bgp + (kb + STAGES - 1) * 16;
            cp16(sa + (uint32_t)(rowA0 * 20 + cA0) * 4u, Ag + (size_t)rowA0 * K + cA0);
            cp16(sa + (uint32_t)(rowA1 * 20 + cA1) * 4u, Ag + (size_t)rowA1 * K + cA1);
            cp16(sa + (uint32_t)(2560 + rowA0 * 20 + cA0) * 4u, Bg + (size_t)rowA0 * K + cA0);
            cp16(sa + (uint32_t)(2560 + rowA1 * 20 + cA1) * 4u, Bg + (size_t)rowA1 * K + cA1);
        }
        asm volatile("cp.async.commit_group;");

        const float* Ab = smem + (kb & (STAGES - 1)) * STG_F;
        const float* Bb = Ab + 2560;
#pragma unroll
        for (int ks = 0; ks < 2; ++ks) {
            const int k0 = ks * 8;
            unsigned af[4][4], bf[4][2];
#pragma unroll
            for (int mt = 0; mt < 4; ++mt) {
                int row = wm * 64 + mt * 16 + fr;
                af[mt][0] = __float_as_uint(Ab[row * 20 + k0 + fc]);
                af[mt][1] = __float_as_uint(Ab[(row + 8) * 20 + k0 + fc]);
                af[mt][2] = __float_as_uint(Ab[row * 20 + k0 + fc + 4]);
                af[mt][3] = __float_as_uint(Ab[(row + 8) * 20 + k0 + fc + 4]);
            }
#pragma unroll
            for (int nt = 0; nt < 4; ++nt) {
                int col = wn * 32 + nt * 8 + fr;
                bf[nt][0] = __float_as_uint(Bb[col * 20 + k0 + fc]);
                bf[nt][1] = __float_as_uint(Bb[col * 20 + k0 + fc + 4]);
            }
#pragma unroll
            for (int mt = 0; mt < 4; ++mt)
#pragma unroll
                for (int nt = 0; nt < 4; ++nt)
                    mma_tf32(acc[mt][nt], af[mt], bf[nt]);
        }
    }

    const int c2 = (lane & 3) * 2;
#pragma unroll
    for (int mt = 0; mt < 4; ++mt) {
        int row = m0 + wm * 64 + mt * 16 + fr;
#pragma unroll
        for (int nt = 0; nt < 4; ++nt) {
            int col = n0 + wn * 32 + nt * 8 + c2;
            size_t i0 = (size_t)row * N + col;
            size_t i1 = (size_t)(row + 8) * N + col;
            float b0 = bias[col], b1 = bias[col + 1];
            float v0 = acc[mt][nt][0] + b0, v1 = acc[mt][nt][1] + b1;
            float v2 = acc[mt][nt][2] + b0, v3 = acc[mt][nt][3] + b1;
            if (RES) {
                float2 r0 = *(const float2*)&Rsrc[i0];
                float2 r1 = *(const float2*)&Rsrc[i1];
                v0 += r0.x; v1 += r0.y; v2 += r1.x; v3 += r1.y;
            }
            if (RELU) { v0 = fmaxf(v0, 0.f); v1 = fmaxf(v1, 0.f); v2 = fmaxf(v2, 0.f); v3 = fmaxf(v3, 0.f); }
            if (ROUND) { v0 = to_tf32(v0); v1 = to_tf32(v1); v2 = to_tf32(v2); v3 = to_tf32(v3); }
            float2 o0 = {v0, v1}, o1 = {v2, v3};
            *(float2*)&C[i0] = o0;
            *(float2*)&C[i1] = o1;
        }
    }
}

/* ---------------- RevIN stats ---------------- */
__global__ void revin_stats_kernel(const float* __restrict__ x, float* __restrict__ mean,
                                   float* __restrict__ stdv) {
    int bm = blockIdx.x;
    int b = bm / MM, m = bm % MM;
    const float* xp = x + (size_t)b * LL * MM + m;
    float s = 0.f, s2 = 0.f;
    for (int l = threadIdx.x; l < LL; l += 256) {
        float v = xp[(size_t)l * MM];
        s += v; s2 += v * v;
    }
    __shared__ float sh0[256], sh1[256];
    sh0[threadIdx.x] = s; sh1[threadIdx.x] = s2;
    __syncthreads();
    for (int off = 128; off > 0; off >>= 1) {
        if (threadIdx.x < off) { sh0[threadIdx.x] += sh0[threadIdx.x + off]; sh1[threadIdx.x] += sh1[threadIdx.x + off]; }
        __syncthreads();
    }
    if (threadIdx.x == 0) {
        float mu = sh0[0] * (1.f / LL);
        float var = sh1[0] * (1.f / LL) - mu * mu;
        mean[bm] = mu;
        stdv[bm] = sqrtf(var + EPSF);
    }
}

/* ---------------- patches ---------------- */
__global__ void patches_kernel(const float* __restrict__ x, const float* __restrict__ mean,
                               const float* __restrict__ stdv, const float* __restrict__ rw,
                               const float* __restrict__ rb, float* __restrict__ patches) {
    int idx = blockIdx.x * 256 + threadIdx.x;
    int p = idx & 15;
    int n = (idx >> 4) & 63;
    int bm = idx >> 10;
    int m = bm % MM;
    int b = bm / MM;
    int l = n * 16 + p;
    float v = x[(size_t)b * LL * MM + (size_t)l * MM + m];
    v = (v - mean[bm]) / stdv[bm] * rw[m] + rb[m];
    patches[idx] = v;
}

/* ---------------- composed spectral transform ---------------- */
__global__ void computeT_kernel(const float* __restrict__ wr, const float* __restrict__ wi,
                                float* __restrict__ T) {
    int lay = blockIdx.x;
    __shared__ float Ur[32][64], Ui[32][64];
    const float* wrp = wr + (size_t)lay * FREQ * A2;
    const float* wip = wi + (size_t)lay * FREQ * A2;
    const float c0 = 6.28318530717958647692f / 64.f;
    for (int e = threadIdx.x; e < 32 * 64; e += 256) {
        int d = e >> 6, n = e & 63;
        float sr = 0.f, si = 0.f;
        for (int kf = 0; kf < FREQ; ++kf) {
            float ang = c0 * (float)(kf * n);
            float cv, sv;
            sincosf(ang, &sv, &cv);
            sr += wrp[kf * A2 + d] * cv;
            si += wip[kf * A2 + d] * (-sv);
        }
        Ur[d][n] = sr; Ui[d][n] = si;
    }
    __syncthreads();
    for (int e = threadIdx.x; e < 64 * 64; e += 256) {
        int a = e >> 6, n = e & 63;
        float tval = Ur[0][n];
        for (int d = 1; d < 32; ++d) {
            float ang = c0 * (float)(d * a);
            float cv, sv;
            sincosf(ang, &sv, &cv);
            tval += 2.f * (Ur[d][n] * cv - Ui[d][n] * sv);
        }
        T[lay * 4096 + e] = tval * (1.f / 64.f);
    }
}

/* ---------------- instance-norm stats ---------------- */
__global__ void pn_stats_kernel(const float* __restrict__ patches, float* __restrict__ mu,
                                float* __restrict__ rv) {
    int idx = blockIdx.x * 256 + threadIdx.x;
    int b = idx >> 10;
    int np = idx & 1023;
    const float* pp = patches + (size_t)b * 21504 + np;
    float s = 0.f, s2 = 0.f;
#pragma unroll
    for (int m = 0; m < MM; ++m) { float v = pp[m * 1024]; s += v; s2 += v * v; }
    float m0 = s * (1.f / MM);
    float var = s2 * (1.f / MM) - m0 * m0;
    mu[idx] = m0;
    rv[idx] = rsqrtf(var + EPSF);
}

/* ---------------- spectral mixing ---------------- */
__global__ void spect_kernel(const float* __restrict__ patches, const float* __restrict__ mu,
                             const float* __restrict__ rv, const float* __restrict__ g,
                             const float* __restrict__ be, const float* __restrict__ T,
                             float* __restrict__ ad) {
    int idx = blockIdx.x * 256 + threadIdx.x;
    int p = idx & 15;
    int a = (idx >> 4) & 63;
    int bm = idx >> 10;
    int m = bm % MM;
    int b = bm / MM;
    float gm = g[m], bm_ = be[m];
    const float* pp  = patches + (size_t)bm * 1024 + p;
    const float* mup = mu + b * 1024 + p;
    const float* rvp = rv + b * 1024 + p;
    const float* Tp  = T + a * 64;
    float acc = 0.f;
#pragma unroll 8
    for (int n = 0; n < 64; ++n) {
        float pn = (pp[n * 16] - mup[n * 16]) * rvp[n * 16] * gm + bm_;
        acc += Tp[n] * pn;
    }
    ad[idx] = acc;
}

/* ---------------- embeddings ---------------- */
template<int ADD>
__global__ __launch_bounds__(256) void embed_kernel(const float* __restrict__ src,
                                                    const float* __restrict__ Hin,
                                                    const float* __restrict__ inw,
                                                    const float* __restrict__ inb,
                                                    float* __restrict__ out) {
    __shared__ float ps[1024];
    int blk = blockIdx.x;
    int t = threadIdx.x;
    const float4* sp = (const float4*)(src + (size_t)blk * 1024);
    ((float4*)ps)[t] = sp[t];
    float w[3][16], bb[3];
#pragma unroll
    for (int j = 0; j < 3; ++j) {
        int c = t + 256 * j;
        bb[j] = inb[c];
#pragma unroll
        for (int p4 = 0; p4 < 4; ++p4) {
            float4 wv = *(const float4*)(inw + (size_t)c * 16 + p4 * 4);
            w[j][p4 * 4] = wv.x; w[j][p4 * 4 + 1] = wv.y; w[j][p4 * 4 + 2] = wv.z; w[j][p4 * 4 + 3] = wv.w;
        }
    }
    __syncthreads();
    size_t rowbase = (size_t)blk * 64 * DD;
    for (int r = 0; r < 64; ++r) {
        float pr[16];
#pragma unroll
        for (int p4 = 0; p4 < 4; ++p4) {
            float4 pv = *(const float4*)&ps[r * 16 + p4 * 4];
            pr[p4 * 4] = pv.x; pr[p4 * 4 + 1] = pv.y; pr[p4 * 4 + 2] = pv.z; pr[p4 * 4 + 3] = pv.w;
        }
        size_t ro = rowbase + (size_t)r * DD;
#pragma unroll
        for (int j = 0; j < 3; ++j) {
            float acc = bb[j];
            if (ADD) acc += Hin[ro + t + 256 * j];
#pragma unroll
            for (int p = 0; p < 16; ++p) acc = fmaf(pr[p], w[j][p], acc);
            out[ro + t + 256 * j] = ADD ? to_tf32(acc) : acc;
        }
    }
}

/* ---------------- attention: tiled scores ---------------- */
__global__ __launch_bounds__(256) void scores_tile_kernel(const float* __restrict__ q,
                                                          const float* __restrict__ k,
                                                          const float* __restrict__ bias,
                                                          float* __restrict__ sc) {
    int bm = blockIdx.x, h = blockIdx.y, sh = blockIdx.z;
    __shared__ float qs[64 * 96];
    __shared__ float ksT[96 * 33];
    int t = threadIdx.x;
    const float* qg = q + (size_t)bm * 64 * DD + h * EE;
    const float* kg = k + (size_t)bm * 64 * DD + h * EE + (size_t)sh * 32 * DD;
    for (int i = t; i < 1536; i += 256) {
        int r = i / 24, c = i % 24;
        ((float4*)qs)[r * 24 + c] = *(const float4*)(qg + (size_t)r * DD + c * 4);
    }
    for (int i = t; i < 768; i += 256) {
        int s = i / 24, c = i % 24;
        float4 v4 = *(const float4*)(kg + (size_t)s * DD + c * 4);
        ksT[(c * 4 + 0) * 33 + s] = v4.x;
        ksT[(c * 4 + 1) * 33 + s] = v4.y;
        ksT[(c * 4 + 2) * 33 + s] = v4.z;
        ksT[(c * 4 + 3) * 33 + s] = v4.w;
    }
    __syncthreads();
    int l0 = (t >> 4) * 4, s0 = (t & 15) * 2;
    float acc[4][2] = {};
    for (int e = 0; e < 96; ++e) {
        float kv0 = ksT[e * 33 + s0], kv1 = ksT[e * 33 + s0 + 1];
#pragma unroll
        for (int i2 = 0; i2 < 4; ++i2) {
            float qv = qs[(l0 + i2) * 96 + e];
            acc[i2][0] = fmaf(qv, kv0, acc[i2][0]);
            acc[i2][1] = fmaf(qv, kv1, acc[i2][1]);
        }
    }
    const float SCALE = 0.10206207261596575f;
    float* scp = sc + (size_t)(bm * 8 + h) * 4096;
#pragma unroll
    for (int i2 = 0; i2 < 4; ++i2)
#pragma unroll
        for (int j = 0; j < 2; ++j) {
            int l = l0 + i2, s = sh * 32 + s0 + j;
            scp[l * 64 + s] = acc[i2][j] * SCALE + bias[(l * 64 + s) * 8 + h];
        }
}

__global__ void softmax_kernel(float* __restrict__ sc) {
    int idx = blockIdx.x * 256 + threadIdx.x;
    float* p = sc + (size_t)idx * 64;
    float mx = -1e30f;
#pragma unroll 8
    for (int s = 0; s < 64; ++s) mx = fmaxf(mx, p[s]);
    float sum = 0.f;
#pragma unroll 8
    for (int s = 0; s < 64; ++s) { float e = expf(p[s] - mx); p[s] = e; sum += e; }
    float inv = 1.f / sum;
#pragma unroll 8
    for (int s = 0; s < 64; ++s) p[s] *= inv;
}

/* ---------------- attention: tiled AV ---------------- */
__global__ __launch_bounds__(256) void av_tile_kernel(const float* __restrict__ sc,
                                                      const float* __restrict__ v,
                                                      float* __restrict__ o) {
    int bm = blockIdx.x, h = blockIdx.y;
    __shared__ float at[64 * 65];
    __shared__ float vs[64 * 96];
    int t = threadIdx.x;
    const float* ap = sc + (size_t)(bm * 8 + h) * 4096;
    const float* vg = v + (size_t)bm * 64 * DD + h * EE;
    for (int i = t; i < 1024; i += 256) {
        int l = i >> 4, c = i & 15;
        float4 a4 = *(const float4*)(ap + l * 64 + c * 4);
        at[l * 65 + c * 4 + 0] = a4.x; at[l * 65 + c * 4 + 1] = a4.y;
        at[l * 65 + c * 4 + 2] = a4.z; at[l * 65 + c * 4 + 3] = a4.w;
    }
    for (int i = t; i < 1536; i += 256) {
        int s = i / 24, c = i % 24;
        *(float4*)&vs[s * 96 + c * 4] = *(const float4*)(vg + (size_t)s * DD + c * 4);
    }
    __syncthreads();
    int l0 = (t >> 4) * 4, e0 = (t & 15) * 6;
    float acc[4][6] = {};
    for (int s = 0; s < 64; ++s) {
        float av_[4], vv[6];
#pragma unroll
        for (int i2 = 0; i2 < 4; ++i2) av_[i2] = at[(l0 + i2) * 65 + s];
#pragma unroll
        for (int j = 0; j < 6; ++j) vv[j] = vs[s * 96 + e0 + j];
#pragma unroll
        for (int i2 = 0; i2 < 4; ++i2)
#pragma unroll
            for (int j = 0; j < 6; ++j) acc[i2][j] = fmaf(av_[i2], vv[j], acc[i2][j]);
    }
    float* op = o + (size_t)bm * 64 * DD + h * EE;
#pragma unroll
    for (int i2 = 0; i2 < 4; ++i2)
#pragma unroll
        for (int j = 0; j < 6; ++j)
            op[(size_t)(l0 + i2) * DD + e0 + j] = to_tf32(acc[i2][j]);
}

/* ---------------- batchnorm ---------------- */
__global__ void zero_kernel(float* __restrict__ p, int n) {
    int idx = blockIdx.x * 256 + threadIdx.x;
    if (idx < n) p[idx] = 0.f;
}

__global__ void bn_reduce_kernel(const float* __restrict__ X, float* __restrict__ sum,
                                 float* __restrict__ sq) {
    int r0 = blockIdx.x * 128;
    float s[3] = {0.f, 0.f, 0.f}, q[3] = {0.f, 0.f, 0.f};
    for (int r = 0; r < 128; ++r) {
        const float* xp = X + (size_t)(r0 + r) * DD;
#pragma unroll
        for (int j = 0; j < 3; ++j) {
            float v = xp[threadIdx.x + j * 256];
            s[j] += v; q[j] += v * v;
        }
    }
#pragma unroll
    for (int j = 0; j < 3; ++j) {
        atomicAdd(&sum[threadIdx.x + j * 256], s[j]);
        atomicAdd(&sq[threadIdx.x + j * 256], q[j]);
    }
}

template<int CVT>
__global__ void bn_apply_kernel(float* __restrict__ X, const float* __restrict__ sum,
                                const float* __restrict__ sq, const float* __restrict__ g,
                                const float* __restrict__ be) {
    int idx = blockIdx.x * 256 + threadIdx.x;
    int c = idx % DD;
    const float inv_n = 1.f / (float)ROWS;
    float mean = sum[c] * inv_n;
    float var = sq[c] * inv_n - mean * mean;
    float v = (X[idx] - mean) * rsqrtf(var + EPSF) * g[c] + be[c];
    X[idx] = CVT ? to_tf32(v) : v;
}

/* ---------------- final projection ---------------- */
__global__ void final_gemm_kernel(const float* __restrict__ hbuf, const float* __restrict__ ow,
                                  float* __restrict__ osmall) {
    __shared__ float hs[8 * 1024];
    int row0 = blockIdx.x * 8;
    int k0 = blockIdx.y * 1024;
    for (int j = threadIdx.x; j < 2048; j += 128) {
        int r = j >> 8, kq = j & 255;
        *(float4*)&hs[r * 1024 + kq * 4] =
            *(const float4*)&hbuf[(size_t)(row0 + r) * 49152 + k0 + kq * 4];
    }
    __syncthreads();
    int p = threadIdx.x;
    if (p < PREDN) {
        float acc[8] = {0.f, 0.f, 0.f, 0.f, 0.f, 0.f, 0.f, 0.f};
        const float* wp = ow + (size_t)p * 49152 + k0;
        for (int kq = 0; kq < 256; ++kq) {
            float4 w4 = *(const float4*)(wp + kq * 4);
#pragma unroll
            for (int r = 0; r < 8; ++r) {
                const float* hr = &hs[r * 1024 + kq * 4];
                acc[r] += hr[0] * w4.x + hr[1] * w4.y + hr[2] * w4.z + hr[3] * w4.w;
            }
        }
#pragma unroll
        for (int r = 0; r < 8; ++r) atomicAdd(&osmall[(row0 + r) * PREDN + p], acc[r]);
    }
}

/* ---------------- de-norm ---------------- */
__global__ void denorm_kernel(const float* __restrict__ osmall, const float* __restrict__ outb,
                              const float* __restrict__ rw, const float* __restrict__ rb,
                              const float* __restrict__ mean, const float* __restrict__ stdv,
                              float* __restrict__ out) {
    int idx = blockIdx.x * 256 + threadIdx.x;
    int m = idx % MM;
    int pr = (idx / MM) % PREDN;
    int b = idx / (MM * PREDN);
    int bm = b * MM + m;
    float v = osmall[bm * PREDN + pr] + outb[pr];
    v = (v - rb[m]) / (rw[m] + 1e-10f);
    out[idx] = v * stdv[bm] + mean[bm];
}

/* ---------------- launcher ---------------- */
extern "C" void kernel_launch(void* const* d_in, const int* in_sizes, int n_in,
                              void* d_out, int out_size) {
    const float* x         = (const float*)d_in[0];
    const float* attn_bias = (const float*)d_in[1];
    const float* revin_w   = (const float*)d_in[2];
    const float* revin_b   = (const float*)d_in[3];
    const float* in_w      = (const float*)d_in[4];
    const float* in_b      = (const float*)d_in[5];
    const float* ln1_g     = (const float*)d_in[6];
    const float* ln1_b     = (const float*)d_in[7];
    const float* spect_wr  = (const float*)d_in[8];
    const float* spect_wi  = (const float*)d_in[9];
    const float* Wq        = (const float*)d_in[10];
    const float* bq        = (const float*)d_in[11];
    const float* Wk        = (const float*)d_in[12];
    const float* bk        = (const float*)d_in[13];
    const float* Wv        = (const float*)d_in[14];
    const float* bv        = (const float*)d_in[15];
    const float* Wo        = (const float*)d_in[16];
    const float* bo        = (const float*)d_in[17];
    const float* c1_w      = (const float*)d_in[18];
    const float* c1_b      = (const float*)d_in[19];
    const float* c2_w      = (const float*)d_in[20];
    const float* c2_b      = (const float*)d_in[21];
    const float* bn1_g     = (const float*)d_in[22];
    const float* bn1_b     = (const float*)d_in[23];
    const float* bn2_g     = (const float*)d_in[24];
    const float* bn2_b     = (const float*)d_in[25];
    const float* norm_g    = (const float*)d_in[26];
    const float* norm_b    = (const float*)d_in[27];
    const float* out_w     = (const float*)d_in[28];
    const float* out_b     = (const float*)d_in[29];

    float* base = nullptr;
    cudaGetSymbolAddress((void**)&base, g_buf);
    float* mean   = base + OFF_MEAN;
    float* stdv   = base + OFF_STD;
    float* patch  = base + OFF_PATCH;
    float* Tm     = base + OFF_T;
    float* mu     = base + OFF_MU;
    float* rv     = base + OFF_RV;
    float* ad     = base + OFF_AD;
    float* bnsum  = base + OFF_BNSUM;
    float* bnsq   = base + OFF_BNSQ;
    float* osmall = base + OFF_OSMALL;
    float* h      = base + OFF_H;
    float* y      = base + OFF_Y;
    float* q      = base + OFF_Q;
    float* k      = base + OFF_K;
    float* v      = base + OFF_V;
    float* o      = base + OFF_O;
    float* sc     = base + OFF_SC;
    float* f4     = base + OFF_F4;
    float* wc     = base + OFF_WCVT;
    float* WCq = wc;                 /* 3x589824 */
    float* WCk = wc + 1769472u;
    float* WCv = wc + 3538944u;
    float* WCo = wc + 5308416u;
    float* WC1 = wc + 7077888u;      /* 3x2359296 */
    float* WC2 = wc + 14155776u;

    static int attr_done = 0;
    cudaFuncSetAttribute(mma_gemm2<0, 0, 0>, cudaFuncAttributeMaxDynamicSharedMemorySize, GSM2);
    cudaFuncSetAttribute(mma_gemm2<0, 1, 0>, cudaFuncAttributeMaxDynamicSharedMemorySize, GSM2);
    cudaFuncSetAttribute(mma_gemm2<1, 0, 1>, cudaFuncAttributeMaxDynamicSharedMemorySize, GSM2);
    (void)attr_done;

    const int TPB = 256;
    const int G_ED = (ROWS * DD) / TPB;

    /* one-time (per launch) weight tf32 conversion */
    wconv_kernel<<<1769472 / TPB, TPB>>>(Wq, WCq, 1769472);
    wconv_kernel<<<1769472 / TPB, TPB>>>(Wk, WCk, 1769472);
    wconv_kernel<<<1769472 / TPB, TPB>>>(Wv, WCv, 1769472);
    wconv_kernel<<<1769472 / TPB, TPB>>>(Wo, WCo, 1769472);
    wconv_kernel<<<7077888 / TPB, TPB>>>(c1_w, WC1, 7077888);
    wconv_kernel<<<7077888 / TPB, TPB>>>(c2_w, WC2, 7077888);

    revin_stats_kernel<<<BMC, TPB>>>(x, mean, stdv);
    patches_kernel<<<344064 / TPB, TPB>>>(x, mean, stdv, revin_w, revin_b, patch);
    computeT_kernel<<<NLAYER, TPB>>>(spect_wr, spect_wi, Tm);
    embed_kernel<0><<<BMC, TPB>>>(patch, nullptr, in_w, in_b, h);

    dim3 gP(DD / 128, ROWS / 128);           /* (6,168) */
    dim3 gF1(FF4 / 128, ROWS / 128);         /* (24,168) */
    dim3 gS(BMC, HH, 2);
    dim3 gAV(BMC, HH);

    for (int i = 0; i < NLAYER; ++i) {
        pn_stats_kernel<<<16384 / TPB, TPB>>>(patch, mu, rv);
        spect_kernel<<<344064 / TPB, TPB>>>(patch, mu, rv, ln1_g + i * MM, ln1_b + i * MM,
                                            Tm + i * 4096, ad);
        embed_kernel<1><<<BMC, TPB>>>(ad, h, in_w, in_b, y);

        mma_gemm2<0, 0, 0><<<gP, TPB, GSM2>>>(y, WCq + (size_t)i * DD * DD, bq + i * DD, nullptr, q, ROWS, DD, DD);
        mma_gemm2<0, 0, 0><<<gP, TPB, GSM2>>>(y, WCk + (size_t)i * DD * DD, bk + i * DD, nullptr, k, ROWS, DD, DD);
        mma_gemm2<0, 0, 0><<<gP, TPB, GSM2>>>(y, WCv + (size_t)i * DD * DD, bv + i * DD, nullptr, v, ROWS, DD, DD);

        scores_tile_kernel<<<gS, TPB>>>(q, k, attn_bias, sc);
        softmax_kernel<<<172032 / TPB, TPB>>>(sc);
        av_tile_kernel<<<gAV, TPB>>>(sc, v, o);

        mma_gemm2<0, 1, 0><<<gP, TPB, GSM2>>>(o, WCo + (size_t)i * DD * DD, bo + i * DD, y, y, ROWS, DD, DD);

        zero_kernel<<<6, TPB>>>(bnsum, 1536);
        bn_reduce_kernel<<<ROWS / 128, TPB>>>(y, bnsum, bnsq);
        bn_apply_kernel<1><<<G_ED, TPB>>>(y, bnsum, bnsq, bn1_g + i * DD, bn1_b + i * DD);

        mma_gemm2<1, 0, 1><<<gF1, TPB, GSM2>>>(y, WC1 + (size_t)i * FF4 * DD, c1_b + i * FF4, nullptr, f4, ROWS, FF4, DD);
        mma_gemm2<0, 1, 0><<<gP, TPB, GSM2>>>(f4, WC2 + (size_t)i * DD * FF4, c2_b + i * DD, y, h, ROWS, DD, FF4);

        zero_kernel<<<6, TPB>>>(bnsum, 1536);
        bn_reduce_kernel<<<ROWS / 128, TPB>>>(h, bnsum, bnsq);
        bn_apply_kernel<0><<<G_ED, TPB>>>(h, bnsum, bnsq, bn2_g + i * DD, bn2_b + i * DD);
    }

    zero_kernel<<<6, TPB>>>(bnsum, 1536);
    bn_reduce_kernel<<<ROWS / 128, TPB>>>(h, bnsum, bnsq);
    bn_apply_kernel<0><<<G_ED, TPB>>>(h, bnsum, bnsq, norm_g, norm_b);

    zero_kernel<<<32256 / TPB, TPB>>>(osmall, 32256);
    final_gemm_kernel<<<dim3(BMC / 8, 48), 128>>>(h, out_w, osmall);
    denorm_kernel<<<32256 / TPB, TPB>>>(osmall, out_b, revin_w, revin_b, mean, stdv,
                                        (float*)d_out);
}

// round 5
// speedup vs baseline: 4.4007x; 1.1359x over previous
#include <cuda_runtime.h>
#include <cuda_bf16.h>
#include <math.h>
#include <stdint.h>

#define BB 16
#define LL 1024
#define MM 21
#define PP 16
#define NN 64
#define DD 768
#define HH 8
#define EE 96
#define FF4 3072
#define NLAYER 3
#define FREQ 33
#define A2 32
#define PREDN 96
#define BMC (BB*MM)          /* 336 */
#define ROWS (BMC*NN)        /* 21504 */
#define EPSF 1e-5f
#define QKVS 2304            /* packed qkv row stride */

/* ---------------- scratch layout (floats) ---------------- */
#define OFF_MEAN   0u
#define OFF_STD    512u
#define OFF_PATCH  1024u
#define OFF_T      345088u
#define OFF_MU     357376u
#define OFF_RV     373760u
#define OFF_AD     390144u
#define OFF_BNSUM  734208u
#define OFF_BNSQ   734976u
#define OFF_OSMALL 735744u
#define OFF_H      768000u
#define OFF_Y      (OFF_H + 16515072u)
#define OFF_QKV    (OFF_Y + 16515072u)          /* ROWS*2304 = 49545216 */
#define OFF_O      (OFF_QKV + 49545216u)
#define OFF_SC     (OFF_O + 16515072u)
#define OFF_F4     (OFF_SC + 11010048u)
#define OFF_WCVT   (OFF_F4 + 66060288u)
/* WCVT: qkv packed 3x1769472, Wo 3x589824, c1 3x2359296, c2 3x2359296 */
#define OFF_BQKV   (OFF_WCVT + 21233664u)
#define TOTAL_F    (OFF_BQKV + 8192u)

__device__ float g_buf[TOTAL_F];

/* ================= helpers ================= */
__device__ __forceinline__ uint32_t s2u(const void* p) {
    uint32_t a;
    asm("{ .reg .u64 t; cvta.to.shared.u64 t, %1; cvt.u32.u64 %0, t; }" : "=r"(a) : "l"(p));
    return a;
}
__device__ __forceinline__ float to_tf32(float x) {
    unsigned u;
    asm("cvt.rna.tf32.f32 %0, %1;" : "=r"(u) : "f"(x));
    return __uint_as_float(u);
}
__device__ __forceinline__ void mma_tf32(float* d, const unsigned* a, const unsigned* b) {
    asm volatile("mma.sync.aligned.m16n8k8.row.col.f32.tf32.tf32.f32 "
                 "{%0,%1,%2,%3},{%4,%5,%6,%7},{%8,%9},{%0,%1,%2,%3};"
                 : "+f"(d[0]), "+f"(d[1]), "+f"(d[2]), "+f"(d[3])
                 : "r"(a[0]), "r"(a[1]), "r"(a[2]), "r"(a[3]), "r"(b[0]), "r"(b[1]));
}
__device__ __forceinline__ void cp16(uint32_t saddr, const void* g) {
    asm volatile("cp.async.ca.shared.global [%0], [%1], 16;" :: "r"(saddr), "l"(g));
}

/* ---------------- weight tf32 conversion (plain + qkv-pack remap) ------------- */
__global__ void wconv_kernel(const float* __restrict__ in, float* __restrict__ out, int n) {
    int idx = blockIdx.x * 256 + threadIdx.x;
    if (idx < n) out[idx] = to_tf32(in[idx]);
}
/* in: [NL,768,768]; out layer i at i*1769472 + part*589824 */
__global__ void wconv_qkv_kernel(const float* __restrict__ in, float* __restrict__ out,
                                 int part) {
    int idx = blockIdx.x * 256 + threadIdx.x;     /* < 1769472 */
    int lay = idx / 589824, w = idx % 589824;
    out[(size_t)lay * 1769472 + (size_t)part * 589824 + w] = to_tf32(in[idx]);
}
__global__ void bpack_kernel(const float* __restrict__ bq, const float* __restrict__ bk,
                             const float* __restrict__ bv, float* __restrict__ out) {
    int idx = blockIdx.x * 256 + threadIdx.x;     /* < 6912 */
    if (idx >= NLAYER * QKVS) return;
    int lay = idx / QKVS, c = idx % QKVS;
    float v;
    if (c < 768) v = bq[lay * 768 + c];
    else if (c < 1536) v = bk[lay * 768 + c - 768];
    else v = bv[lay * 768 + c - 1536];
    out[idx] = v;
}

/* =========== cp.async 4-stage tf32 mma GEMM, 64x64 warp tiles ===========
   C[M,N] = A[M,K] @ W[N,K]^T + bias (+Rsrc)(relu)(round)
   CTA 128x128, 4 warps (2x2), warp tile 64x64, K-step 16, 128 threads. */
#define STAGES 4
#define STG_F  5120
#define GSM2   (STAGES * STG_F * 4)       /* 81920 bytes */

template<int RELU, int RES, int ROUND>
__global__ __launch_bounds__(128, 2) void mma_gemm3(const float* __restrict__ A,
                                                    const float* __restrict__ W,
                                                    const float* __restrict__ bias,
                                                    const float* __restrict__ Rsrc,
                                                    float* __restrict__ C,
                                                    int M, int N, int K) {
    extern __shared__ float smem[];
    const int t = threadIdx.x;
    const int wid = t >> 5, lane = t & 31;
    const int wm = wid >> 1, wn = wid & 1;       /* 2x2 warps, 64x64 each */
    const int m0 = blockIdx.y * 128, n0 = blockIdx.x * 128;
    const int fr = lane >> 2, fc = lane & 3;
    const uint32_t sbase = s2u(smem);

    const int rowc = t >> 2;                     /* 0..31 */
    const int colc = (t & 3) << 2;               /* 0,4,8,12 */
    const float* Agp = A + (size_t)m0 * K;
    const float* Bgp = W + (size_t)n0 * K;

    float acc[4][8][4];
#pragma unroll
    for (int i = 0; i < 4; ++i)
#pragma unroll
        for (int j = 0; j < 8; ++j)
#pragma unroll
            for (int r = 0; r < 4; ++r) acc[i][j][r] = 0.f;

    const int NT = K >> 4;

#pragma unroll
    for (int s = 0; s < STAGES - 1; ++s) {
        uint32_t sa = sbase + (uint32_t)(s * STG_F) * 4u;
        const float* Ag = Agp + s * 16;
        const float* Bg = Bgp + s * 16;
#pragma unroll
        for (int rr = 0; rr < 4; ++rr) {
            int row = rowc + rr * 32;
            cp16(sa + (uint32_t)(row * 20 + colc) * 4u, Ag + (size_t)row * K + colc);
            cp16(sa + (uint32_t)(2560 + row * 20 + colc) * 4u, Bg + (size_t)row * K + colc);
        }
        asm volatile("cp.async.commit_group;");
    }

    for (int kb = 0; kb < NT; ++kb) {
        asm volatile("cp.async.wait_group %0;" :: "n"(STAGES - 2));
        __syncthreads();
        if (kb + STAGES - 1 < NT) {
            int ss = (kb + STAGES - 1) & (STAGES - 1);
            uint32_t sa = sbase + (uint32_t)(ss * STG_F) * 4u;
            const float* Ag = Agp + (kb + STAGES - 1) * 16;
            const float* Bg = Bgp + (kb + STAGES - 1) * 16;
#pragma unroll
            for (int rr = 0; rr < 4; ++rr) {
                int row = rowc + rr * 32;
                cp16(sa + (uint32_t)(row * 20 + colc) * 4u, Ag + (size_t)row * K + colc);
                cp16(sa + (uint32_t)(2560 + row * 20 + colc) * 4u, Bg + (size_t)row * K + colc);
            }
        }
        asm volatile("cp.async.commit_group;");

        const float* Ab = smem + (kb & (STAGES - 1)) * STG_F;
        const float* Bb = Ab + 2560;
#pragma unroll
        for (int ks = 0; ks < 2; ++ks) {
            const int k0 = ks * 8;
            unsigned af[4][4], bf[8][2];
#pragma unroll
            for (int mt = 0; mt < 4; ++mt) {
                int row = wm * 64 + mt * 16 + fr;
                af[mt][0] = __float_as_uint(Ab[row * 20 + k0 + fc]);
                af[mt][1] = __float_as_uint(Ab[(row + 8) * 20 + k0 + fc]);
                af[mt][2] = __float_as_uint(Ab[row * 20 + k0 + fc + 4]);
                af[mt][3] = __float_as_uint(Ab[(row + 8) * 20 + k0 + fc + 4]);
            }
#pragma unroll
            for (int nt = 0; nt < 8; ++nt) {
                int col = wn * 64 + nt * 8 + fr;
                bf[nt][0] = __float_as_uint(Bb[col * 20 + k0 + fc]);
                bf[nt][1] = __float_as_uint(Bb[col * 20 + k0 + fc + 4]);
            }
#pragma unroll
            for (int mt = 0; mt < 4; ++mt)
#pragma unroll
                for (int nt = 0; nt < 8; ++nt)
                    mma_tf32(acc[mt][nt], af[mt], bf[nt]);
        }
    }

    const int c2 = (lane & 3) * 2;
#pragma unroll
    for (int mt = 0; mt < 4; ++mt) {
        int row = m0 + wm * 64 + mt * 16 + fr;
#pragma unroll
        for (int nt = 0; nt < 8; ++nt) {
            int col = n0 + wn * 64 + nt * 8 + c2;
            size_t i0 = (size_t)row * N + col;
            size_t i1 = (size_t)(row + 8) * N + col;
            float b0 = bias[col], b1 = bias[col + 1];
            float v0 = acc[mt][nt][0] + b0, v1 = acc[mt][nt][1] + b1;
            float v2 = acc[mt][nt][2] + b0, v3 = acc[mt][nt][3] + b1;
            if (RES) {
                float2 r0 = *(const float2*)&Rsrc[i0];
                float2 r1 = *(const float2*)&Rsrc[i1];
                v0 += r0.x; v1 += r0.y; v2 += r1.x; v3 += r1.y;
            }
            if (RELU) { v0 = fmaxf(v0, 0.f); v1 = fmaxf(v1, 0.f); v2 = fmaxf(v2, 0.f); v3 = fmaxf(v3, 0.f); }
            if (ROUND) { v0 = to_tf32(v0); v1 = to_tf32(v1); v2 = to_tf32(v2); v3 = to_tf32(v3); }
            float2 o0 = {v0, v1}, o1 = {v2, v3};
            *(float2*)&C[i0] = o0;
            *(float2*)&C[i1] = o1;
        }
    }
}

/* ---------------- RevIN stats ---------------- */
__global__ void revin_stats_kernel(const float* __restrict__ x, float* __restrict__ mean,
                                   float* __restrict__ stdv) {
    int bm = blockIdx.x;
    int b = bm / MM, m = bm % MM;
    const float* xp = x + (size_t)b * LL * MM + m;
    float s = 0.f, s2 = 0.f;
    for (int l = threadIdx.x; l < LL; l += 256) {
        float v = xp[(size_t)l * MM];
        s += v; s2 += v * v;
    }
    __shared__ float sh0[256], sh1[256];
    sh0[threadIdx.x] = s; sh1[threadIdx.x] = s2;
    __syncthreads();
    for (int off = 128; off > 0; off >>= 1) {
        if (threadIdx.x < off) { sh0[threadIdx.x] += sh0[threadIdx.x + off]; sh1[threadIdx.x] += sh1[threadIdx.x + off]; }
        __syncthreads();
    }
    if (threadIdx.x == 0) {
        float mu = sh0[0] * (1.f / LL);
        float var = sh1[0] * (1.f / LL) - mu * mu;
        mean[bm] = mu;
        stdv[bm] = sqrtf(var + EPSF);
    }
}

/* ---------------- patches ---------------- */
__global__ void patches_kernel(const float* __restrict__ x, const float* __restrict__ mean,
                               const float* __restrict__ stdv, const float* __restrict__ rw,
                               const float* __restrict__ rb, float* __restrict__ patches) {
    int idx = blockIdx.x * 256 + threadIdx.x;
    int p = idx & 15;
    int n = (idx >> 4) & 63;
    int bm = idx >> 10;
    int m = bm % MM;
    int b = bm / MM;
    int l = n * 16 + p;
    float v = x[(size_t)b * LL * MM + (size_t)l * MM + m];
    v = (v - mean[bm]) / stdv[bm] * rw[m] + rb[m];
    patches[idx] = v;
}

/* ---------------- composed spectral transform ---------------- */
__global__ void computeT_kernel(const float* __restrict__ wr, const float* __restrict__ wi,
                                float* __restrict__ T) {
    int lay = blockIdx.x;
    __shared__ float Ur[32][64], Ui[32][64];
    const float* wrp = wr + (size_t)lay * FREQ * A2;
    const float* wip = wi + (size_t)lay * FREQ * A2;
    const float c0 = 6.28318530717958647692f / 64.f;
    for (int e = threadIdx.x; e < 32 * 64; e += 256) {
        int d = e >> 6, n = e & 63;
        float sr = 0.f, si = 0.f;
        for (int kf = 0; kf < FREQ; ++kf) {
            float ang = c0 * (float)(kf * n);
            float cv, sv;
            sincosf(ang, &sv, &cv);
            sr += wrp[kf * A2 + d] * cv;
            si += wip[kf * A2 + d] * (-sv);
        }
        Ur[d][n] = sr; Ui[d][n] = si;
    }
    __syncthreads();
    for (int e = threadIdx.x; e < 64 * 64; e += 256) {
        int a = e >> 6, n = e & 63;
        float tval = Ur[0][n];
        for (int d = 1; d < 32; ++d) {
            float ang = c0 * (float)(d * a);
            float cv, sv;
            sincosf(ang, &sv, &cv);
            tval += 2.f * (Ur[d][n] * cv - Ui[d][n] * sv);
        }
        T[lay * 4096 + e] = tval * (1.f / 64.f);
    }
}

/* ---------------- instance-norm stats ---------------- */
__global__ void pn_stats_kernel(const float* __restrict__ patches, float* __restrict__ mu,
                                float* __restrict__ rv) {
    int idx = blockIdx.x * 256 + threadIdx.x;
    int b = idx >> 10;
    int np = idx & 1023;
    const float* pp = patches + (size_t)b * 21504 + np;
    float s = 0.f, s2 = 0.f;
#pragma unroll
    for (int m = 0; m < MM; ++m) { float v = pp[m * 1024]; s += v; s2 += v * v; }
    float m0 = s * (1.f / MM);
    float var = s2 * (1.f / MM) - m0 * m0;
    mu[idx] = m0;
    rv[idx] = rsqrtf(var + EPSF);
}

/* ---------------- spectral mixing ---------------- */
__global__ void spect_kernel(const float* __restrict__ patches, const float* __restrict__ mu,
                             const float* __restrict__ rv, const float* __restrict__ g,
                             const float* __restrict__ be, const float* __restrict__ T,
                             float* __restrict__ ad) {
    int idx = blockIdx.x * 256 + threadIdx.x;
    int p = idx & 15;
    int a = (idx >> 4) & 63;
    int bm = idx >> 10;
    int m = bm % MM;
    int b = bm / MM;
    float gm = g[m], bm_ = be[m];
    const float* pp  = patches + (size_t)bm * 1024 + p;
    const float* mup = mu + b * 1024 + p;
    const float* rvp = rv + b * 1024 + p;
    const float* Tp  = T + a * 64;
    float acc = 0.f;
#pragma unroll 8
    for (int n = 0; n < 64; ++n) {
        float pn = (pp[n * 16] - mup[n * 16]) * rvp[n * 16] * gm + bm_;
        acc += Tp[n] * pn;
    }
    ad[idx] = acc;
}

/* ---------------- embeddings ---------------- */
template<int ADD>
__global__ __launch_bounds__(256) void embed_kernel(const float* __restrict__ src,
                                                    const float* __restrict__ Hin,
                                                    const float* __restrict__ inw,
                                                    const float* __restrict__ inb,
                                                    float* __restrict__ out) {
    __shared__ float ps[1024];
    int blk = blockIdx.x;
    int t = threadIdx.x;
    const float4* sp = (const float4*)(src + (size_t)blk * 1024);
    ((float4*)ps)[t] = sp[t];
    float w[3][16], bb[3];
#pragma unroll
    for (int j = 0; j < 3; ++j) {
        int c = t + 256 * j;
        bb[j] = inb[c];
#pragma unroll
        for (int p4 = 0; p4 < 4; ++p4) {
            float4 wv = *(const float4*)(inw + (size_t)c * 16 + p4 * 4);
            w[j][p4 * 4] = wv.x; w[j][p4 * 4 + 1] = wv.y; w[j][p4 * 4 + 2] = wv.z; w[j][p4 * 4 + 3] = wv.w;
        }
    }
    __syncthreads();
    size_t rowbase = (size_t)blk * 64 * DD;
    for (int r = 0; r < 64; ++r) {
        float pr[16];
#pragma unroll
        for (int p4 = 0; p4 < 4; ++p4) {
            float4 pv = *(const float4*)&ps[r * 16 + p4 * 4];
            pr[p4 * 4] = pv.x; pr[p4 * 4 + 1] = pv.y; pr[p4 * 4 + 2] = pv.z; pr[p4 * 4 + 3] = pv.w;
        }
        size_t ro = rowbase + (size_t)r * DD;
#pragma unroll
        for (int j = 0; j < 3; ++j) {
            float acc = bb[j];
            if (ADD) acc += Hin[ro + t + 256 * j];
#pragma unroll
            for (int p = 0; p < 16; ++p) acc = fmaf(pr[p], w[j][p], acc);
            out[ro + t + 256 * j] = ADD ? to_tf32(acc) : acc;
        }
    }
}

/* ---------------- attention: tiled scores (qkv packed, stride 2304) ------------- */
__global__ __launch_bounds__(256) void scores_tile_kernel(const float* __restrict__ qkv,
                                                          const float* __restrict__ bias,
                                                          float* __restrict__ sc) {
    int bm = blockIdx.x, h = blockIdx.y, sh = blockIdx.z;
    __shared__ float qs[64 * 96];
    __shared__ float ksT[96 * 33];
    int t = threadIdx.x;
    const float* qg = qkv + (size_t)bm * 64 * QKVS + h * EE;
    const float* kg = qkv + (size_t)bm * 64 * QKVS + 768 + h * EE + (size_t)sh * 32 * QKVS;
    for (int i = t; i < 1536; i += 256) {
        int r = i / 24, c = i % 24;
        ((float4*)qs)[r * 24 + c] = *(const float4*)(qg + (size_t)r * QKVS + c * 4);
    }
    for (int i = t; i < 768; i += 256) {
        int s = i / 24, c = i % 24;
        float4 v4 = *(const float4*)(kg + (size_t)s * QKVS + c * 4);
        ksT[(c * 4 + 0) * 33 + s] = v4.x;
        ksT[(c * 4 + 1) * 33 + s] = v4.y;
        ksT[(c * 4 + 2) * 33 + s] = v4.z;
        ksT[(c * 4 + 3) * 33 + s] = v4.w;
    }
    __syncthreads();
    int l0 = (t >> 4) * 4, s0 = (t & 15) * 2;
    float acc[4][2] = {};
    for (int e = 0; e < 96; ++e) {
        float kv0 = ksT[e * 33 + s0], kv1 = ksT[e * 33 + s0 + 1];
#pragma unroll
        for (int i2 = 0; i2 < 4; ++i2) {
            float qv = qs[(l0 + i2) * 96 + e];
            acc[i2][0] = fmaf(qv, kv0, acc[i2][0]);
            acc[i2][1] = fmaf(qv, kv1, acc[i2][1]);
        }
    }
    const float SCALE = 0.10206207261596575f;
    float* scp = sc + (size_t)(bm * 8 + h) * 4096;
#pragma unroll
    for (int i2 = 0; i2 < 4; ++i2)
#pragma unroll
        for (int j = 0; j < 2; ++j) {
            int l = l0 + i2, s = sh * 32 + s0 + j;
            scp[l * 64 + s] = acc[i2][j] * SCALE + bias[(l * 64 + s) * 8 + h];
        }
}

__global__ void softmax_kernel(float* __restrict__ sc) {
    int idx = blockIdx.x * 256 + threadIdx.x;
    float* p = sc + (size_t)idx * 64;
    float mx = -1e30f;
#pragma unroll 8
    for (int s = 0; s < 64; ++s) mx = fmaxf(mx, p[s]);
    float sum = 0.f;
#pragma unroll 8
    for (int s = 0; s < 64; ++s) { float e = expf(p[s] - mx); p[s] = e; sum += e; }
    float inv = 1.f / sum;
#pragma unroll 8
    for (int s = 0; s < 64; ++s) p[s] *= inv;
}

/* ---------------- attention: tiled AV ---------------- */
__global__ __launch_bounds__(256) void av_tile_kernel(const float* __restrict__ sc,
                                                      const float* __restrict__ qkv,
                                                      float* __restrict__ o) {
    int bm = blockIdx.x, h = blockIdx.y;
    __shared__ float at[64 * 65];
    __shared__ float vs[64 * 96];
    int t = threadIdx.x;
    const float* ap = sc + (size_t)(bm * 8 + h) * 4096;
    const float* vg = qkv + (size_t)bm * 64 * QKVS + 1536 + h * EE;
    for (int i = t; i < 1024; i += 256) {
        int l = i >> 4, c = i & 15;
        float4 a4 = *(const float4*)(ap + l * 64 + c * 4);
        at[l * 65 + c * 4 + 0] = a4.x; at[l * 65 + c * 4 + 1] = a4.y;
        at[l * 65 + c * 4 + 2] = a4.z; at[l * 65 + c * 4 + 3] = a4.w;
    }
    for (int i = t; i < 1536; i += 256) {
        int s = i / 24, c = i % 24;
        *(float4*)&vs[s * 96 + c * 4] = *(const float4*)(vg + (size_t)s * QKVS + c * 4);
    }
    __syncthreads();
    int l0 = (t >> 4) * 4, e0 = (t & 15) * 6;
    float acc[4][6] = {};
    for (int s = 0; s < 64; ++s) {
        float av_[4], vv[6];
#pragma unroll
        for (int i2 = 0; i2 < 4; ++i2) av_[i2] = at[(l0 + i2) * 65 + s];
#pragma unroll
        for (int j = 0; j < 6; ++j) vv[j] = vs[s * 96 + e0 + j];
#pragma unroll
        for (int i2 = 0; i2 < 4; ++i2)
#pragma unroll
            for (int j = 0; j < 6; ++j) acc[i2][j] = fmaf(av_[i2], vv[j], acc[i2][j]);
    }
    float* op = o + (size_t)bm * 64 * DD + h * EE;
#pragma unroll
    for (int i2 = 0; i2 < 4; ++i2)
#pragma unroll
        for (int j = 0; j < 6; ++j)
            op[(size_t)(l0 + i2) * DD + e0 + j] = to_tf32(acc[i2][j]);
}

/* ---------------- batchnorm ---------------- */
__global__ void zero_kernel(float* __restrict__ p, int n) {
    int idx = blockIdx.x * 256 + threadIdx.x;
    if (idx < n) p[idx] = 0.f;
}

__global__ void bn_reduce_kernel(const float* __restrict__ X, float* __restrict__ sum,
                                 float* __restrict__ sq) {
    int r0 = blockIdx.x * 128;
    float s[3] = {0.f, 0.f, 0.f}, q[3] = {0.f, 0.f, 0.f};
    for (int r = 0; r < 128; ++r) {
        const float* xp = X + (size_t)(r0 + r) * DD;
#pragma unroll
        for (int j = 0; j < 3; ++j) {
            float v = xp[threadIdx.x + j * 256];
            s[j] += v; q[j] += v * v;
        }
    }
#pragma unroll
    for (int j = 0; j < 3; ++j) {
        atomicAdd(&sum[threadIdx.x + j * 256], s[j]);
        atomicAdd(&sq[threadIdx.x + j * 256], q[j]);
    }
}

template<int CVT>
__global__ void bn_apply_kernel(float* __restrict__ X, const float* __restrict__ sum,
                                const float* __restrict__ sq, const float* __restrict__ g,
                                const float* __restrict__ be) {
    int idx = blockIdx.x * 256 + threadIdx.x;
    int c = idx % DD;
    const float inv_n = 1.f / (float)ROWS;
    float mean = sum[c] * inv_n;
    float var = sq[c] * inv_n - mean * mean;
    float v = (X[idx] - mean) * rsqrtf(var + EPSF) * g[c] + be[c];
    X[idx] = CVT ? to_tf32(v) : v;
}

/* ---------------- final projection ---------------- */
__global__ void final_gemm_kernel(const float* __restrict__ hbuf, const float* __restrict__ ow,
                                  float* __restrict__ osmall) {
    __shared__ float hs[8 * 1024];
    int row0 = blockIdx.x * 8;
    int k0 = blockIdx.y * 1024;
    for (int j = threadIdx.x; j < 2048; j += 128) {
        int r = j >> 8, kq = j & 255;
        *(float4*)&hs[r * 1024 + kq * 4] =
            *(const float4*)&hbuf[(size_t)(row0 + r) * 49152 + k0 + kq * 4];
    }
    __syncthreads();
    int p = threadIdx.x;
    if (p < PREDN) {
        float acc[8] = {0.f, 0.f, 0.f, 0.f, 0.f, 0.f, 0.f, 0.f};
        const float* wp = ow + (size_t)p * 49152 + k0;
        for (int kq = 0; kq < 256; ++kq) {
            float4 w4 = *(const float4*)(wp + kq * 4);
#pragma unroll
            for (int r = 0; r < 8; ++r) {
                const float* hr = &hs[r * 1024 + kq * 4];
                acc[r] += hr[0] * w4.x + hr[1] * w4.y + hr[2] * w4.z + hr[3] * w4.w;
            }
        }
#pragma unroll
        for (int r = 0; r < 8; ++r) atomicAdd(&osmall[(row0 + r) * PREDN + p], acc[r]);
    }
}

/* ---------------- de-norm ---------------- */
__global__ void denorm_kernel(const float* __restrict__ osmall, const float* __restrict__ outb,
                              const float* __restrict__ rw, const float* __restrict__ rb,
                              const float* __restrict__ mean, const float* __restrict__ stdv,
                              float* __restrict__ out) {
    int idx = blockIdx.x * 256 + threadIdx.x;
    int m = idx % MM;
    int pr = (idx / MM) % PREDN;
    int b = idx / (MM * PREDN);
    int bm = b * MM + m;
    float v = osmall[bm * PREDN + pr] + outb[pr];
    v = (v - rb[m]) / (rw[m] + 1e-10f);
    out[idx] = v * stdv[bm] + mean[bm];
}

/* ---------------- launcher ---------------- */
extern "C" void kernel_launch(void* const* d_in, const int* in_sizes, int n_in,
                              void* d_out, int out_size) {
    const float* x         = (const float*)d_in[0];
    const float* attn_bias = (const float*)d_in[1];
    const float* revin_w   = (const float*)d_in[2];
    const float* revin_b   = (const float*)d_in[3];
    const float* in_w      = (const float*)d_in[4];
    const float* in_b      = (const float*)d_in[5];
    const float* ln1_g     = (const float*)d_in[6];
    const float* ln1_b     = (const float*)d_in[7];
    const float* spect_wr  = (const float*)d_in[8];
    const float* spect_wi  = (const float*)d_in[9];
    const float* Wq        = (const float*)d_in[10];
    const float* bq        = (const float*)d_in[11];
    const float* Wk        = (const float*)d_in[12];
    const float* bk        = (const float*)d_in[13];
    const float* Wv        = (const float*)d_in[14];
    const float* bv        = (const float*)d_in[15];
    const float* Wo        = (const float*)d_in[16];
    const float* bo        = (const float*)d_in[17];
    const float* c1_w      = (const float*)d_in[18];
    const float* c1_b      = (const float*)d_in[19];
    const float* c2_w      = (const float*)d_in[20];
    const float* c2_b      = (const float*)d_in[21];
    const float* bn1_g     = (const float*)d_in[22];
    const float* bn1_b     = (const float*)d_in[23];
    const float* bn2_g     = (const float*)d_in[24];
    const float* bn2_b     = (const float*)d_in[25];
    const float* norm_g    = (const float*)d_in[26];
    const float* norm_b    = (const float*)d_in[27];
    const float* out_w     = (const float*)d_in[28];
    const float* out_b     = (const float*)d_in[29];

    float* base = nullptr;
    cudaGetSymbolAddress((void**)&base, g_buf);
    float* mean   = base + OFF_MEAN;
    float* stdv   = base + OFF_STD;
    float* patch  = base + OFF_PATCH;
    float* Tm     = base + OFF_T;
    float* mu     = base + OFF_MU;
    float* rv     = base + OFF_RV;
    float* ad     = base + OFF_AD;
    float* bnsum  = base + OFF_BNSUM;
    float* bnsq   = base + OFF_BNSQ;
    float* osmall = base + OFF_OSMALL;
    float* h      = base + OFF_H;
    float* y      = base + OFF_Y;
    float* qkv    = base + OFF_QKV;
    float* o      = base + OFF_O;
    float* sc     = base + OFF_SC;
    float* f4     = base + OFF_F4;
    float* wc     = base + OFF_WCVT;
    float* WCqkv = wc;               /* 3 x 1769472 (packed q,k,v) */
    float* WCo   = wc + 5308416u;    /* 3 x 589824 */
    float* WC1   = wc + 7077888u;    /* 3 x 2359296 */
    float* WC2   = wc + 14155776u;
    float* bqkv  = base + OFF_BQKV;

    cudaFuncSetAttribute(mma_gemm3<0, 0, 0>, cudaFuncAttributeMaxDynamicSharedMemorySize, GSM2);
    cudaFuncSetAttribute(mma_gemm3<0, 1, 0>, cudaFuncAttributeMaxDynamicSharedMemorySize, GSM2);
    cudaFuncSetAttribute(mma_gemm3<1, 0, 1>, cudaFuncAttributeMaxDynamicSharedMemorySize, GSM2);

    const int TPB = 256;
    const int G_ED = (ROWS * DD) / TPB;

    /* weight conversion + packing */
    wconv_qkv_kernel<<<1769472 / TPB, TPB>>>(Wq, WCqkv, 0);
    wconv_qkv_kernel<<<1769472 / TPB, TPB>>>(Wk, WCqkv, 1);
    wconv_qkv_kernel<<<1769472 / TPB, TPB>>>(Wv, WCqkv, 2);
    wconv_kernel<<<1769472 / TPB, TPB>>>(Wo, WCo, 1769472);
    wconv_kernel<<<7077888 / TPB, TPB>>>(c1_w, WC1, 7077888);
    wconv_kernel<<<7077888 / TPB, TPB>>>(c2_w, WC2, 7077888);
    bpack_kernel<<<27, TPB>>>(bq, bk, bv, bqkv);

    revin_stats_kernel<<<BMC, TPB>>>(x, mean, stdv);
    patches_kernel<<<344064 / TPB, TPB>>>(x, mean, stdv, revin_w, revin_b, patch);
    computeT_kernel<<<NLAYER, TPB>>>(spect_wr, spect_wi, Tm);
    embed_kernel<0><<<BMC, TPB>>>(patch, nullptr, in_w, in_b, h);

    dim3 gQKV(QKVS / 128, ROWS / 128);       /* (18,168) */
    dim3 gP(DD / 128, ROWS / 128);           /* (6,168) */
    dim3 gF1(FF4 / 128, ROWS / 128);         /* (24,168) */
    dim3 gS(BMC, HH, 2);
    dim3 gAV(BMC, HH);

    for (int i = 0; i < NLAYER; ++i) {
        pn_stats_kernel<<<16384 / TPB, TPB>>>(patch, mu, rv);
        spect_kernel<<<344064 / TPB, TPB>>>(patch, mu, rv, ln1_g + i * MM, ln1_b + i * MM,
                                            Tm + i * 4096, ad);
        embed_kernel<1><<<BMC, TPB>>>(ad, h, in_w, in_b, y);

        mma_gemm3<0, 0, 0><<<gQKV, 128, GSM2>>>(y, WCqkv + (size_t)i * 1769472u,
                                                bqkv + i * QKVS, nullptr, qkv, ROWS, QKVS, DD);

        scores_tile_kernel<<<gS, TPB>>>(qkv, attn_bias, sc);
        softmax_kernel<<<172032 / TPB, TPB>>>(sc);
        av_tile_kernel<<<gAV, TPB>>>(sc, qkv, o);

        mma_gemm3<0, 1, 0><<<gP, 128, GSM2>>>(o, WCo + (size_t)i * DD * DD, bo + i * DD, y, y, ROWS, DD, DD);

        zero_kernel<<<6, TPB>>>(bnsum, 1536);
        bn_reduce_kernel<<<ROWS / 128, TPB>>>(y, bnsum, bnsq);
        bn_apply_kernel<1><<<G_ED, TPB>>>(y, bnsum, bnsq, bn1_g + i * DD, bn1_b + i * DD);

        mma_gemm3<1, 0, 1><<<gF1, 128, GSM2>>>(y, WC1 + (size_t)i * FF4 * DD, c1_b + i * FF4, nullptr, f4, ROWS, FF4, DD);
        mma_gemm3<0, 1, 0><<<gP, 128, GSM2>>>(f4, WC2 + (size_t)i * DD * FF4, c2_b + i * DD, y, h, ROWS, DD, FF4);

        zero_kernel<<<6, TPB>>>(bnsum, 1536);
        bn_reduce_kernel<<<ROWS / 128, TPB>>>(h, bnsum, bnsq);
        bn_apply_kernel<0><<<G_ED, TPB>>>(h, bnsum, bnsq, bn2_g + i * DD, bn2_b + i * DD);
    }

    zero_kernel<<<6, TPB>>>(bnsum, 1536);
    bn_reduce_kernel<<<ROWS / 128, TPB>>>(h, bnsum, bnsq);
    bn_apply_kernel<0><<<G_ED, TPB>>>(h, bnsum, bnsq, norm_g, norm_b);

    zero_kernel<<<32256 / TPB, TPB>>>(osmall, 32256);
    final_gemm_kernel<<<dim3(BMC / 8, 48), 128>>>(h, out_w, osmall);
    denorm_kernel<<<32256 / TPB, TPB>>>(osmall, out_b, revin_w, revin_b, mean, stdv,
                                        (float*)d_out);
}